// round 12
// baseline (speedup 1.0000x reference)
#include <cuda_runtime.h>
#include <cuda_fp16.h>
#include <cstdint>

// RankOnePlanes, round 12: fp16 main product (exact: mask-split operands,
// fp32 accum) + e4m3 fp8 correction MMA (corr = fl*w + f*wl, tolerant of
// fp8's 2^-4 rounding since corr ~ 2^-10 of H). 4 MMAs per np8 step vs 6
// (R9-R11) -> tensor floor ~28us; vs R8's unsafe single product, rel_err
// drops ~9e-4 -> ~2e-4. k-axis of the corr GEMM is permuted so each lane's
// fp8 A fragment = exactly its 8 computed channels; fp8 B fragments
// precomputed per (np8,lane) in smem (8KB, 1 conflict-free LDS.128/step).

#define LTAB 128
#define CL 32
#define HDIM 128
#define TSTRIDE 36   // floats per table row (4 x 32B quarter-blocks + 16B pad)
#define NTHREADS 256
#define WARPS_PER_CTA 8
#define NBLOCKS 304  // 2 per SM
#define ROWPAD 80    // W1 fp16 (wh) row bytes: 64B data + 16B pad
#define TILE_M 32

// ---- smem byte offsets ----
#define SM_TAB 0                          // 3*128*36*4 = 55296
#define SM_W1  55296                      // 128 * 80   = 10240
#define SM_BW  65536                      // 64 float4  = 1024
#define SM_F8B 66560                      // 16*32*16B  = 8192
#define SMEM_BYTES 74752                  // x2 CTAs = 149.5 KB/SM

typedef unsigned long long ull;

__device__ __forceinline__ uint32_t smem_u32(const void* p) {
    uint32_t a;
    asm("{ .reg .u64 t; cvta.to.shared.u64 t, %1; cvt.u32.u64 %0, t; }"
        : "=r"(a) : "l"(p));
    return a;
}
__device__ __forceinline__ void ldsm_x4(uint32_t addr, uint32_t* r) {
    asm volatile("ldmatrix.sync.aligned.m8n8.x4.shared.b16 {%0,%1,%2,%3}, [%4];"
                 : "=r"(r[0]), "=r"(r[1]), "=r"(r[2]), "=r"(r[3]) : "r"(addr));
}
__device__ __forceinline__ void mma_f16(float4& c, const uint32_t* a,
                                        const uint32_t* b) {
    asm volatile(
        "mma.sync.aligned.m16n8k16.row.col.f32.f16.f16.f32 "
        "{%0,%1,%2,%3}, {%4,%5,%6,%7}, {%8,%9}, {%0,%1,%2,%3};"
        : "+f"(c.x), "+f"(c.y), "+f"(c.z), "+f"(c.w)
        : "r"(a[0]), "r"(a[1]), "r"(a[2]), "r"(a[3]), "r"(b[0]), "r"(b[1]));
}
// fp8 e4m3 correction MMA: m16n8k32, fp32 accumulate
__device__ __forceinline__ void mma_f8(float4& c, const uint32_t* a,
                                       uint32_t b0, uint32_t b1) {
    asm volatile(
        "mma.sync.aligned.m16n8k32.row.col.f32.e4m3.e4m3.f32 "
        "{%0,%1,%2,%3}, {%4,%5,%6,%7}, {%8,%9}, {%0,%1,%2,%3};"
        : "+f"(c.x), "+f"(c.y), "+f"(c.z), "+f"(c.w)
        : "r"(a[0]), "r"(a[1]), "r"(a[2]), "r"(a[3]), "r"(b0), "r"(b1));
}
// pack (lo, hi) floats -> f16x2 (lo in low half)
__device__ __forceinline__ uint32_t pkh(float lo, float hi) {
    uint32_t r;
    asm("cvt.rn.f16x2.f32 %0, %1, %2;" : "=r"(r) : "f"(hi), "f"(lo));
    return r;
}
// pack 4 floats -> 4x e4m3 (f0 in byte 0)
__device__ __forceinline__ uint32_t pk8_4(float f0, float f1, float f2, float f3) {
    unsigned short a, b;
    asm("cvt.rn.satfinite.e4m3x2.f32 %0, %1, %2;" : "=h"(a) : "f"(f1), "f"(f0));
    asm("cvt.rn.satfinite.e4m3x2.f32 %0, %1, %2;" : "=h"(b) : "f"(f3), "f"(f2));
    return (uint32_t)a | ((uint32_t)b << 16);
}
// ---- f32x2 packed helpers ----
__device__ __forceinline__ ull pk2(float lo, float hi) {
    ull r;
    asm("mov.b64 %0, {%1, %2};" : "=l"(r) : "f"(lo), "f"(hi));
    return r;
}
__device__ __forceinline__ void unpk2(float& lo, float& hi, ull v) {
    asm("mov.b64 {%0, %1}, %2;" : "=f"(lo), "=f"(hi) : "l"(v));
}
__device__ __forceinline__ ull mul2(ull a, ull b) {
    ull d;
    asm("mul.rn.f32x2 %0, %1, %2;" : "=l"(d) : "l"(a), "l"(b));
    return d;
}
__device__ __forceinline__ ull add2(ull a, ull b) {
    ull d;
    asm("add.rn.f32x2 %0, %1, %2;" : "=l"(d) : "l"(a), "l"(b));
    return d;
}
__device__ __forceinline__ ull sub2(ull a, ull b) {
    ull d;
    asm("sub.rn.f32x2 %0, %1, %2;" : "=l"(d) : "l"(a), "l"(b));
    return d;
}
__device__ __forceinline__ ull fma2(ull a, ull b, ull c) {
    ull d;
    asm("fma.rn.f32x2 %0, %1, %2, %3;" : "=l"(d) : "l"(a), "l"(b), "l"(c));
    return d;
}
__device__ __forceinline__ ull and64(ull a, ull m) {
    ull d;
    asm("and.b64 %0, %1, %2;" : "=l"(d) : "l"(a), "l"(m));
    return d;
}

__device__ __forceinline__ void sample_setup(float c, int& r0, int& r1,
                                             float& w0, float& w1) {
    float pos = (c + 1.0f) * 63.5f;
    float f0  = floorf(pos);
    float fr  = pos - f0;
    int i0 = (int)f0;
    int i1 = i0 + 1;
    w0 = ((unsigned)i0 < (unsigned)LTAB) ? (1.0f - fr) : 0.0f;
    w1 = ((unsigned)i1 < (unsigned)LTAB) ? fr : 0.0f;
    r0 = min(max(i0, 0), LTAB - 1);
    r1 = min(max(i1, 0), LTAB - 1);
}

// 8 features of one point (this lane's quarter-block channels), f32x2 math.
// Returns the 4 f32x2 pairs.
__device__ __forceinline__ void feats8_poly(const float* __restrict__ sT, int qoff,
                                            float cx, float cy, float cz,
                                            ull* __restrict__ fp) {
    int xr0, xr1, yr0, yr1, zr0, zr1;
    float xw0, xw1, yw0, yw1, zw0, zw1;
    sample_setup(cx, xr0, xr1, xw0, xw1);
    sample_setup(cy, yr0, yr1, yw0, yw1);
    sample_setup(cz, zr0, zr1, zw0, zw1);

    const ulonglong2* X0 = reinterpret_cast<const ulonglong2*>(&sT[(0 * LTAB + xr0) * TSTRIDE + qoff]);
    const ulonglong2* X1 = reinterpret_cast<const ulonglong2*>(&sT[(0 * LTAB + xr1) * TSTRIDE + qoff]);
    const ulonglong2* Y0 = reinterpret_cast<const ulonglong2*>(&sT[(1 * LTAB + yr0) * TSTRIDE + qoff]);
    const ulonglong2* Y1 = reinterpret_cast<const ulonglong2*>(&sT[(1 * LTAB + yr1) * TSTRIDE + qoff]);
    const ulonglong2* Z0 = reinterpret_cast<const ulonglong2*>(&sT[(2 * LTAB + zr0) * TSTRIDE + qoff]);
    const ulonglong2* Z1 = reinterpret_cast<const ulonglong2*>(&sT[(2 * LTAB + zr1) * TSTRIDE + qoff]);

    const ull xw0p = pk2(xw0, xw0), xw1p = pk2(xw1, xw1);
    const ull yw0p = pk2(yw0, yw0), yw1p = pk2(yw1, yw1);
    const ull zw0p = pk2(zw0, zw0), zw1p = pk2(zw1, zw1);
    const ull invRp  = 0x4020000040200000ull;  // {2.5f, 2.5f}
    const ull invR2p = 0x40C8000040C80000ull;  // {6.25f, 6.25f}

    ulonglong2 x0 = X0[0], x0b = X0[1];
    ulonglong2 x1 = X1[0], x1b = X1[1];
    ulonglong2 y0 = Y0[0], y0b = Y0[1];
    ulonglong2 y1 = Y1[0], y1b = Y1[1];
    ulonglong2 z0 = Z0[0], z0b = Z0[1];
    ulonglong2 z1 = Z1[0], z1b = Z1[1];

    ull xp[4] = {x0.x, x0.y, x0b.x, x0b.y};
    ull xq[4] = {x1.x, x1.y, x1b.x, x1b.y};
    ull yp[4] = {y0.x, y0.y, y0b.x, y0b.y};
    ull yq[4] = {y1.x, y1.y, y1b.x, y1b.y};
    ull zp[4] = {z0.x, z0.y, z0b.x, z0b.y};
    ull zq[4] = {z1.x, z1.y, z1b.x, z1b.y};

#pragma unroll
    for (int pr = 0; pr < 4; pr++) {
        ull xv = fma2(xq[pr], xw1p, mul2(xp[pr], xw0p));
        ull yv = fma2(yq[pr], yw1p, mul2(yp[pr], yw0p));
        ull zv = fma2(zq[pr], zw1p, mul2(zp[pr], zw0p));
        ull e  = add2(xv, yv);
        ull s  = add2(e, zv);
        ull xy = mul2(xv, yv);
        ull p2 = fma2(zv, e, xy);
        ull p3 = mul2(xy, zv);
        ull f  = fma2(p2, invRp, s);
        fp[pr] = fma2(p3, invR2p, f);
    }
}

__device__ __forceinline__ float mask_hi(float w) {
    return __int_as_float(__float_as_int(w) & 0xFFFFE000);
}

__global__ __launch_bounds__(NTHREADS, 2)
void rank1_hmma_kernel(const float* __restrict__ coords,
                       const float* __restrict__ lines,
                       const float* __restrict__ W1,
                       const float* __restrict__ b1,
                       const float* __restrict__ W2,
                       const float* __restrict__ b2,
                       float* __restrict__ out, int M) {
    extern __shared__ char smc[];
    float* sT = reinterpret_cast<float*>(smc + SM_TAB);
    float4* sBW = reinterpret_cast<float4*>(smc + SM_BW);
    uint4* sF8B = reinterpret_cast<uint4*>(smc + SM_F8B);
    const uint32_t sb = smem_u32(smc);

    const int tid  = threadIdx.x;
    const int wid  = tid >> 5;
    const int lane = tid & 31;

    // ---- stage table: per row, 4 quarter-blocks of 8 permuted channels ----
    // block q holds channels {2q,2q+1,2q+8,2q+9,2q+16,2q+17,2q+24,2q+25}
    for (int idx = tid; idx < 3 * LTAB; idx += NTHREADS) {
        const float* src = lines + idx * CL;
        float v[CL];
#pragma unroll
        for (int j = 0; j < 8; j++) {
            float4 t4 = reinterpret_cast<const float4*>(src)[j];
            v[4 * j + 0] = t4.x; v[4 * j + 1] = t4.y;
            v[4 * j + 2] = t4.z; v[4 * j + 3] = t4.w;
        }
        float* dst = sT + idx * TSTRIDE;
#pragma unroll
        for (int q = 0; q < 4; q++) {
            dst[8 * q + 0] = v[2 * q];      dst[8 * q + 1] = v[2 * q + 1];
            dst[8 * q + 2] = v[2 * q + 8];  dst[8 * q + 3] = v[2 * q + 9];
            dst[8 * q + 4] = v[2 * q + 16]; dst[8 * q + 5] = v[2 * q + 17];
            dst[8 * q + 6] = v[2 * q + 24]; dst[8 * q + 7] = v[2 * q + 25];
        }
    }
    // ---- stage fp16 wh rows (mask-split high part of W1) ----
    if (tid < HDIM) {
        char* dst = smc + SM_W1 + tid * ROWPAD;
        const float4* wrow = reinterpret_cast<const float4*>(W1 + tid * CL);
#pragma unroll
        for (int j = 0; j < 8; j += 2) {
            float4 wa = wrow[j], wb = wrow[j + 1];
            uint4 vh = make_uint4(
                pkh(mask_hi(wa.x), mask_hi(wa.y)),
                pkh(mask_hi(wa.z), mask_hi(wa.w)),
                pkh(mask_hi(wb.x), mask_hi(wb.y)),
                pkh(mask_hi(wb.z), mask_hi(wb.w)));
            *reinterpret_cast<uint4*>(dst + j * 8) = vh;
        }
    }
    // ---- stage packed (b1,b1',W2,W2') per column pair ----
    if (tid < HDIM / 2) {
        sBW[tid] = make_float4(b1[2 * tid], b1[2 * tid + 1],
                               W2[2 * tid], W2[2 * tid + 1]);
    }
    // ---- stage fp8 B fragments: entry (np8 i, lane l) ----
    // MMA#1: B = e4m3(w * 2^6) at permuted-k channels; MMA#2: B = e4m3(wl * 2^9)
    for (int e = tid; e < 16 * 32; e += NTHREADS) {
        int i = e >> 5, l = e & 31;
        int q = l & 3;
        int n = 8 * i + (l >> 2);
        const float* wr = W1 + n * CL + 2 * q;
        float2 p0 = *reinterpret_cast<const float2*>(wr);
        float2 p1 = *reinterpret_cast<const float2*>(wr + 8);
        float2 p2 = *reinterpret_cast<const float2*>(wr + 16);
        float2 p3 = *reinterpret_cast<const float2*>(wr + 24);
        // B#1: w * 2^6, channel order lo = {2q,2q+1,2q+8,2q+9}, hi = +16
        uint32_t b10 = pk8_4(p0.x * 64.f, p0.y * 64.f, p1.x * 64.f, p1.y * 64.f);
        uint32_t b11 = pk8_4(p2.x * 64.f, p2.y * 64.f, p3.x * 64.f, p3.y * 64.f);
        // B#2: wl * 2^9
        float l0 = (p0.x - mask_hi(p0.x)) * 512.f, l1 = (p0.y - mask_hi(p0.y)) * 512.f;
        float l2 = (p1.x - mask_hi(p1.x)) * 512.f, l3 = (p1.y - mask_hi(p1.y)) * 512.f;
        float l4 = (p2.x - mask_hi(p2.x)) * 512.f, l5 = (p2.y - mask_hi(p2.y)) * 512.f;
        float l6 = (p3.x - mask_hi(p3.x)) * 512.f, l7 = (p3.y - mask_hi(p3.y)) * 512.f;
        uint32_t b20 = pk8_4(l0, l1, l2, l3);
        uint32_t b21 = pk8_4(l4, l5, l6, l7);
        sF8B[e] = make_uint4(b10, b11, b20, b21);
    }
    __syncthreads();

    const float bias2 = __ldg(b2);
    const uint32_t b_addr_base =
        (sb + SM_W1) + (uint32_t)(lane & 7) * ROWPAD + (uint32_t)(lane >> 3) * 16;

    const int qoff = (lane & 3) * 8;
    const int base = lane >> 2;

    const int warp_gid    = blockIdx.x * WARPS_PER_CTA + wid;
    const int total_warps = NBLOCKS * WARPS_PER_CTA;
    const int tiles       = (M + TILE_M - 1) / TILE_M;

    const ull hmask = 0xFFFFE000FFFFE000ull;
    const ull s9p   = 0x4400000044000000ull;  // {512, 512}
    const ull s6p   = 0x4280000042800000ull;  // {64, 64}

    for (int t = warp_gid; t < tiles; t += total_warps) {
        // ---- build A fragments: 4 points per lane ----
        uint32_t afr[2][2][4];   // fp16 fh  [row-tile][k16-chunk][frag reg]
        uint32_t a8l[2][4];      // e4m3 fl*2^9  [row-tile][frag reg]
        uint32_t a8h[2][4];      // e4m3 f*2^6
#pragma unroll
        for (int pi = 0; pi < 4; pi++) {
            int p  = t * TILE_M + base + pi * 8;
            int pc = (p < M) ? p : (M - 1);
            float cx = __ldg(&coords[3 * pc + 0]);
            float cy = __ldg(&coords[3 * pc + 1]);
            float cz = __ldg(&coords[3 * pc + 2]);
            ull fp[4];
            feats8_poly(sT, qoff, cx, cy, cz, fp);

            int rt = pi >> 1;
            int rs = pi & 1;
            float v0, v1;
            float fl[8], fs[8];
#pragma unroll
            for (int pr = 0; pr < 4; pr++) {
                ull fh  = and64(fp[pr], hmask);
                ull flp = mul2(sub2(fp[pr], fh), s9p);   // fl * 2^9
                ull fsp = mul2(fp[pr], s6p);             // f  * 2^6
                unpk2(v0, v1, fh);
                uint32_t h = pkh(v0, v1);
                if (pr == 0) { afr[rt][0][rs] = h; }
                else if (pr == 1) { afr[rt][0][2 + rs] = h; }
                else if (pr == 2) { afr[rt][1][rs] = h; }
                else { afr[rt][1][2 + rs] = h; }
                unpk2(fl[2 * pr], fl[2 * pr + 1], flp);
                unpk2(fs[2 * pr], fs[2 * pr + 1], fsp);
            }
            a8l[rt][rs]     = pk8_4(fl[0], fl[1], fl[2], fl[3]);
            a8l[rt][2 + rs] = pk8_4(fl[4], fl[5], fl[6], fl[7]);
            a8h[rt][rs]     = pk8_4(fs[0], fs[1], fs[2], fs[3]);
            a8h[rt][2 + rs] = pk8_4(fs[4], fs[5], fs[6], fs[7]);
        }

        float oacc[4] = {0.f, 0.f, 0.f, 0.f};

#pragma unroll
        for (int np8 = 0; np8 < 16; np8++) {
            uint32_t bwh[4];
            ldsm_x4(b_addr_base + (uint32_t)(np8 * 8) * ROWPAD, bwh);
            uint4 f8b = sF8B[np8 * 32 + lane];
            float4 bw = sBW[np8 * 4 + (lane & 3)];

#pragma unroll
            for (int rt = 0; rt < 2; rt++) {
                float4 c = make_float4(bw.x, bw.y, bw.x, bw.y);  // bias init
                mma_f16(c, afr[rt][0], &bwh[0]);   // fh*wh k0
                mma_f16(c, afr[rt][1], &bwh[2]);   // fh*wh k1
                float4 d = make_float4(0.f, 0.f, 0.f, 0.f);
                mma_f8(d, a8l[rt], f8b.x, f8b.y);  // (fl*2^9)*(w*2^6)
                mma_f8(d, a8h[rt], f8b.z, f8b.w);  // (f*2^6)*(wl*2^9)
                const float inv15 = 3.0517578125e-05f;  // 2^-15
                float hx = fmaf(d.x, inv15, c.x);
                float hy = fmaf(d.y, inv15, c.y);
                float hz = fmaf(d.z, inv15, c.z);
                float hw = fmaf(d.w, inv15, c.w);
                oacc[2 * rt + 0] = fmaf(fmaxf(hx, 0.f), bw.z, oacc[2 * rt + 0]);
                oacc[2 * rt + 0] = fmaf(fmaxf(hy, 0.f), bw.w, oacc[2 * rt + 0]);
                oacc[2 * rt + 1] = fmaf(fmaxf(hz, 0.f), bw.z, oacc[2 * rt + 1]);
                oacc[2 * rt + 1] = fmaf(fmaxf(hw, 0.f), bw.w, oacc[2 * rt + 1]);
            }
        }

        // ---- reduce over the 4 lanes sharing each row, then store ----
#pragma unroll
        for (int i = 0; i < 4; i++) {
            oacc[i] += __shfl_xor_sync(0xffffffffu, oacc[i], 1);
            oacc[i] += __shfl_xor_sync(0xffffffffu, oacc[i], 2);
        }
        if ((lane & 3) == 0) {
            int pb = t * TILE_M + base;
            if (pb      < M) out[pb]      = oacc[0] + bias2;
            if (pb + 8  < M) out[pb + 8]  = oacc[1] + bias2;
            if (pb + 16 < M) out[pb + 16] = oacc[2] + bias2;
            if (pb + 24 < M) out[pb + 24] = oacc[3] + bias2;
        }
    }
}

extern "C" void kernel_launch(void* const* d_in, const int* in_sizes, int n_in,
                              void* d_out, int out_size) {
    const float* coords = (const float*)d_in[0];
    const float* lines  = (const float*)d_in[1];
    const float* W1     = (const float*)d_in[2];
    const float* b1     = (const float*)d_in[3];
    const float* W2     = (const float*)d_in[4];
    const float* b2     = (const float*)d_in[5];
    float* out = (float*)d_out;

    int M = in_sizes[0] / 3;

    cudaFuncSetAttribute(rank1_hmma_kernel,
                         cudaFuncAttributeMaxDynamicSharedMemorySize, SMEM_BYTES);

    rank1_hmma_kernel<<<NBLOCKS, NTHREADS, SMEM_BYTES>>>(
        coords, lines, W1, b1, W2, b2, out, M);
}

// round 13
// speedup vs baseline: 1.3863x; 1.3863x over previous
#include <cuda_runtime.h>
#include <cuda_fp16.h>
#include <cstdint>

// RankOnePlanes, round 13: 4-MMA precision scheme at near-R8 cost.
//  - feature side EXACT: mask-split f = fh + fl (both fp16-exact), products
//    fh*wh + fl*wh reuse the SAME B registers (no extra LDSM/staging).
//  - weight side FREE: f*wl ~= fbar*wl (folded exactly into b1' at staging,
//    fbar = E[f] = 1.74375) + (f-fbar)*wl residual ~1.6e-4.
//  vs R8 (9.1e-4, 1.1x gate margin): adds only 2 MMAs/step + ~3% scalar.
//  vs R9-R12 6-MMA-equivalent floor: 2 fewer MMA-equivalents (~14us).

#define LTAB 128
#define CL 32
#define HDIM 128
#define TSTRIDE 36   // floats per table row (4 x 32B quarter-blocks + 16B pad)
#define NTHREADS 256
#define WARPS_PER_CTA 8
#define NBLOCKS 456  // 3 per SM (R8's winning occupancy)
#define ROWPAD 80    // W1 fp16 (wh) row bytes: 64B data + 16B pad
#define TILE_M 32
#define FBAR 1.74375f  // E[f]: tables U[0.1,0.5] -> 0.9 + 0.675 + 0.169

// ---- smem byte offsets ----
#define SM_TAB  0                         // 3*128*36*4 = 55296
#define SM_W1   55296                     // 128 * 80   = 10240
#define SM_BW   65536                     // 64 float4  = 1024
#define SM_B1P  66560                     // 128 float  = 512
#define SMEM_BYTES 67072                  // x3 CTAs = 201.2 KB/SM

typedef unsigned long long ull;

__device__ __forceinline__ uint32_t smem_u32(const void* p) {
    uint32_t a;
    asm("{ .reg .u64 t; cvta.to.shared.u64 t, %1; cvt.u32.u64 %0, t; }"
        : "=r"(a) : "l"(p));
    return a;
}
__device__ __forceinline__ void ldsm_x4(uint32_t addr, uint32_t* r) {
    asm volatile("ldmatrix.sync.aligned.m8n8.x4.shared.b16 {%0,%1,%2,%3}, [%4];"
                 : "=r"(r[0]), "=r"(r[1]), "=r"(r[2]), "=r"(r[3]) : "r"(addr));
}
__device__ __forceinline__ void mma_f16(float4& c, const uint32_t* a,
                                        const uint32_t* b) {
    asm volatile(
        "mma.sync.aligned.m16n8k16.row.col.f32.f16.f16.f32 "
        "{%0,%1,%2,%3}, {%4,%5,%6,%7}, {%8,%9}, {%0,%1,%2,%3};"
        : "+f"(c.x), "+f"(c.y), "+f"(c.z), "+f"(c.w)
        : "r"(a[0]), "r"(a[1]), "r"(a[2]), "r"(a[3]), "r"(b[0]), "r"(b[1]));
}
// pack (lo, hi) floats -> f16x2 (lo in low half)
__device__ __forceinline__ uint32_t pkh(float lo, float hi) {
    uint32_t r;
    asm("cvt.rn.f16x2.f32 %0, %1, %2;" : "=r"(r) : "f"(hi), "f"(lo));
    return r;
}
// ---- f32x2 packed helpers ----
__device__ __forceinline__ ull pk2(float lo, float hi) {
    ull r;
    asm("mov.b64 %0, {%1, %2};" : "=l"(r) : "f"(lo), "f"(hi));
    return r;
}
__device__ __forceinline__ void unpk2(float& lo, float& hi, ull v) {
    asm("mov.b64 {%0, %1}, %2;" : "=f"(lo), "=f"(hi) : "l"(v));
}
__device__ __forceinline__ ull mul2(ull a, ull b) {
    ull d;
    asm("mul.rn.f32x2 %0, %1, %2;" : "=l"(d) : "l"(a), "l"(b));
    return d;
}
__device__ __forceinline__ ull add2(ull a, ull b) {
    ull d;
    asm("add.rn.f32x2 %0, %1, %2;" : "=l"(d) : "l"(a), "l"(b));
    return d;
}
__device__ __forceinline__ ull sub2(ull a, ull b) {
    ull d;
    asm("sub.rn.f32x2 %0, %1, %2;" : "=l"(d) : "l"(a), "l"(b));
    return d;
}
__device__ __forceinline__ ull fma2(ull a, ull b, ull c) {
    ull d;
    asm("fma.rn.f32x2 %0, %1, %2, %3;" : "=l"(d) : "l"(a), "l"(b), "l"(c));
    return d;
}
__device__ __forceinline__ ull and64(ull a, ull m) {
    ull d;
    asm("and.b64 %0, %1, %2;" : "=l"(d) : "l"(a), "l"(m));
    return d;
}

__device__ __forceinline__ void sample_setup(float c, int& r0, int& r1,
                                             float& w0, float& w1) {
    float pos = (c + 1.0f) * 63.5f;
    float f0  = floorf(pos);
    float fr  = pos - f0;
    int i0 = (int)f0;
    int i1 = i0 + 1;
    w0 = ((unsigned)i0 < (unsigned)LTAB) ? (1.0f - fr) : 0.0f;
    w1 = ((unsigned)i1 < (unsigned)LTAB) ? fr : 0.0f;
    r0 = min(max(i0, 0), LTAB - 1);
    r1 = min(max(i1, 0), LTAB - 1);
}

// 8 features of one point (this lane's quarter-block channels), f32x2 math,
// mask-split into fp16-exact (fh, fl) fragment registers.
__device__ __forceinline__ void feats8_hl(const float* __restrict__ sT, int qoff,
                                          float cx, float cy, float cz,
                                          uint32_t* __restrict__ hreg,
                                          uint32_t* __restrict__ lreg) {
    int xr0, xr1, yr0, yr1, zr0, zr1;
    float xw0, xw1, yw0, yw1, zw0, zw1;
    sample_setup(cx, xr0, xr1, xw0, xw1);
    sample_setup(cy, yr0, yr1, yw0, yw1);
    sample_setup(cz, zr0, zr1, zw0, zw1);

    const ulonglong2* X0 = reinterpret_cast<const ulonglong2*>(&sT[(0 * LTAB + xr0) * TSTRIDE + qoff]);
    const ulonglong2* X1 = reinterpret_cast<const ulonglong2*>(&sT[(0 * LTAB + xr1) * TSTRIDE + qoff]);
    const ulonglong2* Y0 = reinterpret_cast<const ulonglong2*>(&sT[(1 * LTAB + yr0) * TSTRIDE + qoff]);
    const ulonglong2* Y1 = reinterpret_cast<const ulonglong2*>(&sT[(1 * LTAB + yr1) * TSTRIDE + qoff]);
    const ulonglong2* Z0 = reinterpret_cast<const ulonglong2*>(&sT[(2 * LTAB + zr0) * TSTRIDE + qoff]);
    const ulonglong2* Z1 = reinterpret_cast<const ulonglong2*>(&sT[(2 * LTAB + zr1) * TSTRIDE + qoff]);

    const ull xw0p = pk2(xw0, xw0), xw1p = pk2(xw1, xw1);
    const ull yw0p = pk2(yw0, yw0), yw1p = pk2(yw1, yw1);
    const ull zw0p = pk2(zw0, zw0), zw1p = pk2(zw1, zw1);
    const ull invRp  = 0x4020000040200000ull;  // {2.5f, 2.5f}
    const ull invR2p = 0x40C8000040C80000ull;  // {6.25f, 6.25f}
    const ull hmask  = 0xFFFFE000FFFFE000ull;  // keep 10 mantissa bits

    ulonglong2 x0 = X0[0], x0b = X0[1];
    ulonglong2 x1 = X1[0], x1b = X1[1];
    ulonglong2 y0 = Y0[0], y0b = Y0[1];
    ulonglong2 y1 = Y1[0], y1b = Y1[1];
    ulonglong2 z0 = Z0[0], z0b = Z0[1];
    ulonglong2 z1 = Z1[0], z1b = Z1[1];

    ull xp[4] = {x0.x, x0.y, x0b.x, x0b.y};
    ull xq[4] = {x1.x, x1.y, x1b.x, x1b.y};
    ull yp[4] = {y0.x, y0.y, y0b.x, y0b.y};
    ull yq[4] = {y1.x, y1.y, y1b.x, y1b.y};
    ull zp[4] = {z0.x, z0.y, z0b.x, z0b.y};
    ull zq[4] = {z1.x, z1.y, z1b.x, z1b.y};

#pragma unroll
    for (int pr = 0; pr < 4; pr++) {
        ull xv = fma2(xq[pr], xw1p, mul2(xp[pr], xw0p));
        ull yv = fma2(yq[pr], yw1p, mul2(yp[pr], yw0p));
        ull zv = fma2(zq[pr], zw1p, mul2(zp[pr], zw0p));
        ull e  = add2(xv, yv);
        ull s  = add2(e, zv);
        ull xy = mul2(xv, yv);
        ull p2 = fma2(zv, e, xy);
        ull p3 = mul2(xy, zv);
        ull f  = fma2(p2, invRp, s);
        f = fma2(p3, invR2p, f);
        ull fh = and64(f, hmask);
        ull fl = sub2(f, fh);
        float a0, a1, b0v, b1v;
        unpk2(a0, a1, fh);
        unpk2(b0v, b1v, fl);
        hreg[pr] = pkh(a0, a1);
        lreg[pr] = pkh(b0v, b1v);
    }
}

__global__ __launch_bounds__(NTHREADS, 3)
void rank1_hmma_kernel(const float* __restrict__ coords,
                       const float* __restrict__ lines,
                       const float* __restrict__ W1,
                       const float* __restrict__ b1,
                       const float* __restrict__ W2,
                       const float* __restrict__ b2,
                       float* __restrict__ out, int M) {
    extern __shared__ char smc[];
    float* sT = reinterpret_cast<float*>(smc + SM_TAB);
    float4* sBW = reinterpret_cast<float4*>(smc + SM_BW);
    float* sB1p = reinterpret_cast<float*>(smc + SM_B1P);
    const uint32_t sb = smem_u32(smc);

    const int tid  = threadIdx.x;
    const int wid  = tid >> 5;
    const int lane = tid & 31;

    // ---- stage table: per row, 4 quarter-blocks of 8 permuted channels ----
    // block q holds channels {2q,2q+1,2q+8,2q+9,2q+16,2q+17,2q+24,2q+25}
    for (int idx = tid; idx < 3 * LTAB; idx += NTHREADS) {
        const float* src = lines + idx * CL;
        float v[CL];
#pragma unroll
        for (int j = 0; j < 8; j++) {
            float4 t4 = reinterpret_cast<const float4*>(src)[j];
            v[4 * j + 0] = t4.x; v[4 * j + 1] = t4.y;
            v[4 * j + 2] = t4.z; v[4 * j + 3] = t4.w;
        }
        float* dst = sT + idx * TSTRIDE;
#pragma unroll
        for (int q = 0; q < 4; q++) {
            dst[8 * q + 0] = v[2 * q];      dst[8 * q + 1] = v[2 * q + 1];
            dst[8 * q + 2] = v[2 * q + 8];  dst[8 * q + 3] = v[2 * q + 9];
            dst[8 * q + 4] = v[2 * q + 16]; dst[8 * q + 5] = v[2 * q + 17];
            dst[8 * q + 6] = v[2 * q + 24]; dst[8 * q + 7] = v[2 * q + 25];
        }
    }
    // ---- stage fp16 wh rows (rn) and fold fbar * sum(wl) into b1 ----
    if (tid < HDIM) {
        char* dst = smc + SM_W1 + tid * ROWPAD;
        const float4* wrow = reinterpret_cast<const float4*>(W1 + tid * CL);
        float s = 0.0f;
#pragma unroll
        for (int j = 0; j < 8; j += 2) {
            float4 wa = wrow[j], wb = wrow[j + 1];
            uint32_t h0 = pkh(wa.x, wa.y), h1 = pkh(wa.z, wa.w);
            uint32_t h2 = pkh(wb.x, wb.y), h3 = pkh(wb.z, wb.w);
            __half2 q0 = *reinterpret_cast<__half2*>(&h0);
            __half2 q1 = *reinterpret_cast<__half2*>(&h1);
            __half2 q2 = *reinterpret_cast<__half2*>(&h2);
            __half2 q3 = *reinterpret_cast<__half2*>(&h3);
            s += (wa.x - __low2float(q0)) + (wa.y - __high2float(q0));
            s += (wa.z - __low2float(q1)) + (wa.w - __high2float(q1));
            s += (wb.x - __low2float(q2)) + (wb.y - __high2float(q2));
            s += (wb.z - __low2float(q3)) + (wb.w - __high2float(q3));
            *reinterpret_cast<uint4*>(dst + j * 8) = make_uint4(h0, h1, h2, h3);
        }
        sB1p[tid] = b1[tid] + FBAR * s;
    }
    __syncthreads();
    // ---- stage packed (b1', b1'', W2, W2') per column pair ----
    if (tid < HDIM / 2) {
        sBW[tid] = make_float4(sB1p[2 * tid], sB1p[2 * tid + 1],
                               W2[2 * tid], W2[2 * tid + 1]);
    }
    __syncthreads();

    const float bias2 = __ldg(b2);
    const uint32_t b_addr_base =
        (sb + SM_W1) + (uint32_t)(lane & 7) * ROWPAD + (uint32_t)(lane >> 3) * 16;

    const int qoff = (lane & 3) * 8;
    const int base = lane >> 2;

    const int warp_gid    = blockIdx.x * WARPS_PER_CTA + wid;
    const int total_warps = NBLOCKS * WARPS_PER_CTA;
    const int tiles       = (M + TILE_M - 1) / TILE_M;

    for (int t = warp_gid; t < tiles; t += total_warps) {
        // ---- build split fp16 A fragments: 4 points per lane ----
        uint32_t afh[2][2][4];   // fh  [row-tile][k16-chunk][frag reg]
        uint32_t afl[2][2][4];   // fl
#pragma unroll
        for (int pi = 0; pi < 4; pi++) {
            int p  = t * TILE_M + base + pi * 8;
            int pc = (p < M) ? p : (M - 1);
            float cx = __ldg(&coords[3 * pc + 0]);
            float cy = __ldg(&coords[3 * pc + 1]);
            float cz = __ldg(&coords[3 * pc + 2]);
            uint32_t h[4], l[4];
            feats8_hl(sT, qoff, cx, cy, cz, h, l);

            int rt = pi >> 1;
            int rs = pi & 1;
            afh[rt][0][rs]     = h[0];   // cols 2q,2q+1       (k chunk 0)
            afh[rt][0][2 + rs] = h[1];   // cols 2q+8,2q+9
            afh[rt][1][rs]     = h[2];   // cols 2q+16,2q+17   (k chunk 1)
            afh[rt][1][2 + rs] = h[3];   // cols 2q+24,2q+25
            afl[rt][0][rs]     = l[0];
            afl[rt][0][2 + rs] = l[1];
            afl[rt][1][rs]     = l[2];
            afl[rt][1][2 + rs] = l[3];
        }

        float oacc[4] = {0.f, 0.f, 0.f, 0.f};

#pragma unroll
        for (int np8 = 0; np8 < 16; np8++) {
            uint32_t bwh[4];  // wh: [k0 lo, k0 hi, k1 lo, k1 hi] of 8 n-rows
            ldsm_x4(b_addr_base + (uint32_t)(np8 * 8) * ROWPAD, bwh);
            float4 bw = sBW[np8 * 4 + (lane & 3)];  // b1',b1'',W2,W2'

#pragma unroll
            for (int rt = 0; rt < 2; rt++) {
                float4 c = make_float4(bw.x, bw.y, bw.x, bw.y);  // bias init
                mma_f16(c, afh[rt][0], &bwh[0]);   // fh*wh k0
                mma_f16(c, afh[rt][1], &bwh[2]);   // fh*wh k1
                mma_f16(c, afl[rt][0], &bwh[0]);   // fl*wh k0  (B regs reused)
                mma_f16(c, afl[rt][1], &bwh[2]);   // fl*wh k1
                oacc[2 * rt + 0] = fmaf(fmaxf(c.x, 0.f), bw.z, oacc[2 * rt + 0]);
                oacc[2 * rt + 0] = fmaf(fmaxf(c.y, 0.f), bw.w, oacc[2 * rt + 0]);
                oacc[2 * rt + 1] = fmaf(fmaxf(c.z, 0.f), bw.z, oacc[2 * rt + 1]);
                oacc[2 * rt + 1] = fmaf(fmaxf(c.w, 0.f), bw.w, oacc[2 * rt + 1]);
            }
        }

        // ---- reduce over the 4 lanes sharing each row, then store ----
#pragma unroll
        for (int i = 0; i < 4; i++) {
            oacc[i] += __shfl_xor_sync(0xffffffffu, oacc[i], 1);
            oacc[i] += __shfl_xor_sync(0xffffffffu, oacc[i], 2);
        }
        if ((lane & 3) == 0) {
            int pb = t * TILE_M + base;
            if (pb      < M) out[pb]      = oacc[0] + bias2;
            if (pb + 8  < M) out[pb + 8]  = oacc[1] + bias2;
            if (pb + 16 < M) out[pb + 16] = oacc[2] + bias2;
            if (pb + 24 < M) out[pb + 24] = oacc[3] + bias2;
        }
    }
}

extern "C" void kernel_launch(void* const* d_in, const int* in_sizes, int n_in,
                              void* d_out, int out_size) {
    const float* coords = (const float*)d_in[0];
    const float* lines  = (const float*)d_in[1];
    const float* W1     = (const float*)d_in[2];
    const float* b1     = (const float*)d_in[3];
    const float* W2     = (const float*)d_in[4];
    const float* b2     = (const float*)d_in[5];
    float* out = (float*)d_out;

    int M = in_sizes[0] / 3;

    cudaFuncSetAttribute(rank1_hmma_kernel,
                         cudaFuncAttributeMaxDynamicSharedMemorySize, SMEM_BYTES);

    rank1_hmma_kernel<<<NBLOCKS, NTHREADS, SMEM_BYTES>>>(
        coords, lines, W1, b1, W2, b2, out, M);
}

// round 14
// speedup vs baseline: 1.5182x; 1.0951x over previous
#include <cuda_runtime.h>
#include <cuda_fp16.h>
#include <cstdint>

// RankOnePlanes, round 14: centered-feature scheme = R8's 2-MMA cost with
// R13-class precision. H = [sum_c fbar_c*W1_c folded EXACTLY into b1, fp32]
// + (f - fbar)*fp16(W1) on tensor cores. fbar_c = per-channel expected
// feature, computed at staging from per-channel table means (axes
// independent -> expectation of the polynomial = polynomial of means).
// Residual errors both have the structure of R13's measured 1.9e-4 term
// -> predicted ~2.7e-4 total (3.7x gate margin) at R8 speed.

#define LTAB 128
#define CL 32
#define HDIM 128
#define TSTRIDE 36   // floats per table row (4 x 32B quarter-blocks + 16B pad)
#define NTHREADS 256
#define WARPS_PER_CTA 8
#define NBLOCKS 456  // 3 per SM
#define ROWPAD 80    // W1 fp16 row bytes: 64B data + 16B pad
#define TILE_M 32

// ---- smem byte offsets ----
#define SM_TAB  0                         // 3*128*36*4 = 55296
#define SM_W1   55296                     // 128 * 80   = 10240
#define SM_BW   65536                     // 64 float4  = 1024
#define SM_B1P  66560                     // 128 float  = 512
#define SM_FBP  67072                     // 32 float (quarter-permuted fbar)
#define SM_FBN  67200                     // 32 float (natural-order fbar)
#define SM_MEAN 67328                     // 96 float (per-axis channel means)
#define SMEM_BYTES 67712                  // x3 CTAs = 203.1 KB/SM

typedef unsigned long long ull;

__device__ __forceinline__ uint32_t smem_u32(const void* p) {
    uint32_t a;
    asm("{ .reg .u64 t; cvta.to.shared.u64 t, %1; cvt.u32.u64 %0, t; }"
        : "=r"(a) : "l"(p));
    return a;
}
__device__ __forceinline__ void ldsm_x4(uint32_t addr, uint32_t* r) {
    asm volatile("ldmatrix.sync.aligned.m8n8.x4.shared.b16 {%0,%1,%2,%3}, [%4];"
                 : "=r"(r[0]), "=r"(r[1]), "=r"(r[2]), "=r"(r[3]) : "r"(addr));
}
__device__ __forceinline__ void mma_f16(float4& c, const uint32_t* a,
                                        const uint32_t* b) {
    asm volatile(
        "mma.sync.aligned.m16n8k16.row.col.f32.f16.f16.f32 "
        "{%0,%1,%2,%3}, {%4,%5,%6,%7}, {%8,%9}, {%0,%1,%2,%3};"
        : "+f"(c.x), "+f"(c.y), "+f"(c.z), "+f"(c.w)
        : "r"(a[0]), "r"(a[1]), "r"(a[2]), "r"(a[3]), "r"(b[0]), "r"(b[1]));
}
// pack (lo, hi) floats -> f16x2 (lo in low half)
__device__ __forceinline__ uint32_t pkh(float lo, float hi) {
    uint32_t r;
    asm("cvt.rn.f16x2.f32 %0, %1, %2;" : "=r"(r) : "f"(hi), "f"(lo));
    return r;
}
// ---- f32x2 packed helpers ----
__device__ __forceinline__ ull pk2(float lo, float hi) {
    ull r;
    asm("mov.b64 %0, {%1, %2};" : "=l"(r) : "f"(lo), "f"(hi));
    return r;
}
__device__ __forceinline__ void unpk2(float& lo, float& hi, ull v) {
    asm("mov.b64 {%0, %1}, %2;" : "=f"(lo), "=f"(hi) : "l"(v));
}
__device__ __forceinline__ ull mul2(ull a, ull b) {
    ull d;
    asm("mul.rn.f32x2 %0, %1, %2;" : "=l"(d) : "l"(a), "l"(b));
    return d;
}
__device__ __forceinline__ ull add2(ull a, ull b) {
    ull d;
    asm("add.rn.f32x2 %0, %1, %2;" : "=l"(d) : "l"(a), "l"(b));
    return d;
}
__device__ __forceinline__ ull sub2(ull a, ull b) {
    ull d;
    asm("sub.rn.f32x2 %0, %1, %2;" : "=l"(d) : "l"(a), "l"(b));
    return d;
}
__device__ __forceinline__ ull fma2(ull a, ull b, ull c) {
    ull d;
    asm("fma.rn.f32x2 %0, %1, %2, %3;" : "=l"(d) : "l"(a), "l"(b), "l"(c));
    return d;
}

__device__ __forceinline__ void sample_setup(float c, int& r0, int& r1,
                                             float& w0, float& w1) {
    float pos = (c + 1.0f) * 63.5f;
    float f0  = floorf(pos);
    float fr  = pos - f0;
    int i0 = (int)f0;
    int i1 = i0 + 1;
    w0 = ((unsigned)i0 < (unsigned)LTAB) ? (1.0f - fr) : 0.0f;
    w1 = ((unsigned)i1 < (unsigned)LTAB) ? fr : 0.0f;
    r0 = min(max(i0, 0), LTAB - 1);
    r1 = min(max(i1, 0), LTAB - 1);
}

// 8 centered features of one point (this lane's quarter-block channels),
// f32x2 math; emits 4 f16x2 fragment registers of (f - fbar).
__device__ __forceinline__ void feats8_c(const float* __restrict__ sT, int qoff,
                                         float cx, float cy, float cz,
                                         const ull* __restrict__ fb2,
                                         uint32_t* __restrict__ hreg) {
    int xr0, xr1, yr0, yr1, zr0, zr1;
    float xw0, xw1, yw0, yw1, zw0, zw1;
    sample_setup(cx, xr0, xr1, xw0, xw1);
    sample_setup(cy, yr0, yr1, yw0, yw1);
    sample_setup(cz, zr0, zr1, zw0, zw1);

    const ulonglong2* X0 = reinterpret_cast<const ulonglong2*>(&sT[(0 * LTAB + xr0) * TSTRIDE + qoff]);
    const ulonglong2* X1 = reinterpret_cast<const ulonglong2*>(&sT[(0 * LTAB + xr1) * TSTRIDE + qoff]);
    const ulonglong2* Y0 = reinterpret_cast<const ulonglong2*>(&sT[(1 * LTAB + yr0) * TSTRIDE + qoff]);
    const ulonglong2* Y1 = reinterpret_cast<const ulonglong2*>(&sT[(1 * LTAB + yr1) * TSTRIDE + qoff]);
    const ulonglong2* Z0 = reinterpret_cast<const ulonglong2*>(&sT[(2 * LTAB + zr0) * TSTRIDE + qoff]);
    const ulonglong2* Z1 = reinterpret_cast<const ulonglong2*>(&sT[(2 * LTAB + zr1) * TSTRIDE + qoff]);

    const ull xw0p = pk2(xw0, xw0), xw1p = pk2(xw1, xw1);
    const ull yw0p = pk2(yw0, yw0), yw1p = pk2(yw1, yw1);
    const ull zw0p = pk2(zw0, zw0), zw1p = pk2(zw1, zw1);
    const ull invRp  = 0x4020000040200000ull;  // {2.5f, 2.5f}
    const ull invR2p = 0x40C8000040C80000ull;  // {6.25f, 6.25f}

    ulonglong2 x0 = X0[0], x0b = X0[1];
    ulonglong2 x1 = X1[0], x1b = X1[1];
    ulonglong2 y0 = Y0[0], y0b = Y0[1];
    ulonglong2 y1 = Y1[0], y1b = Y1[1];
    ulonglong2 z0 = Z0[0], z0b = Z0[1];
    ulonglong2 z1 = Z1[0], z1b = Z1[1];

    ull xp[4] = {x0.x, x0.y, x0b.x, x0b.y};
    ull xq[4] = {x1.x, x1.y, x1b.x, x1b.y};
    ull yp[4] = {y0.x, y0.y, y0b.x, y0b.y};
    ull yq[4] = {y1.x, y1.y, y1b.x, y1b.y};
    ull zp[4] = {z0.x, z0.y, z0b.x, z0b.y};
    ull zq[4] = {z1.x, z1.y, z1b.x, z1b.y};

#pragma unroll
    for (int pr = 0; pr < 4; pr++) {
        ull xv = fma2(xq[pr], xw1p, mul2(xp[pr], xw0p));
        ull yv = fma2(yq[pr], yw1p, mul2(yp[pr], yw0p));
        ull zv = fma2(zq[pr], zw1p, mul2(zp[pr], zw0p));
        ull e  = add2(xv, yv);
        ull s  = add2(e, zv);
        ull xy = mul2(xv, yv);
        ull p2 = fma2(zv, e, xy);
        ull p3 = mul2(xy, zv);
        ull f  = fma2(p2, invRp, s);
        f = fma2(p3, invR2p, f);
        f = sub2(f, fb2[pr]);        // center: f' = f - fbar_c
        float a0, a1;
        unpk2(a0, a1, f);
        hreg[pr] = pkh(a0, a1);
    }
}

__global__ __launch_bounds__(NTHREADS, 3)
void rank1_hmma_kernel(const float* __restrict__ coords,
                       const float* __restrict__ lines,
                       const float* __restrict__ W1,
                       const float* __restrict__ b1,
                       const float* __restrict__ W2,
                       const float* __restrict__ b2,
                       float* __restrict__ out, int M) {
    extern __shared__ char smc[];
    float* sT    = reinterpret_cast<float*>(smc + SM_TAB);
    float4* sBW  = reinterpret_cast<float4*>(smc + SM_BW);
    float* sB1p  = reinterpret_cast<float*>(smc + SM_B1P);
    float* sFBp  = reinterpret_cast<float*>(smc + SM_FBP);
    float* sFBn  = reinterpret_cast<float*>(smc + SM_FBN);
    float* sMean = reinterpret_cast<float*>(smc + SM_MEAN);
    const uint32_t sb = smem_u32(smc);

    const int tid  = threadIdx.x;
    const int wid  = tid >> 5;
    const int lane = tid & 31;

    // ---- stage table: per row, 4 quarter-blocks of 8 permuted channels ----
    // block q holds channels {2q,2q+1,2q+8,2q+9,2q+16,2q+17,2q+24,2q+25}
    for (int idx = tid; idx < 3 * LTAB; idx += NTHREADS) {
        const float* src = lines + idx * CL;
        float v[CL];
#pragma unroll
        for (int j = 0; j < 8; j++) {
            float4 t4 = reinterpret_cast<const float4*>(src)[j];
            v[4 * j + 0] = t4.x; v[4 * j + 1] = t4.y;
            v[4 * j + 2] = t4.z; v[4 * j + 3] = t4.w;
        }
        float* dst = sT + idx * TSTRIDE;
#pragma unroll
        for (int q = 0; q < 4; q++) {
            dst[8 * q + 0] = v[2 * q];      dst[8 * q + 1] = v[2 * q + 1];
            dst[8 * q + 2] = v[2 * q + 8];  dst[8 * q + 3] = v[2 * q + 9];
            dst[8 * q + 4] = v[2 * q + 16]; dst[8 * q + 5] = v[2 * q + 17];
            dst[8 * q + 6] = v[2 * q + 24]; dst[8 * q + 7] = v[2 * q + 25];
        }
    }
    // ---- stage fp16 W1 rows (rn) ----
    if (tid < HDIM) {
        char* dst = smc + SM_W1 + tid * ROWPAD;
        const float4* wrow = reinterpret_cast<const float4*>(W1 + tid * CL);
#pragma unroll
        for (int j = 0; j < 8; j += 2) {
            float4 wa = wrow[j], wb = wrow[j + 1];
            *reinterpret_cast<uint4*>(dst + j * 8) =
                make_uint4(pkh(wa.x, wa.y), pkh(wa.z, wa.w),
                           pkh(wb.x, wb.y), pkh(wb.z, wb.w));
        }
    }
    // ---- per-axis, per-channel table means (coalesced column sums) ----
    if (tid < 96) {
        const float* col = lines + tid * LTAB * 0;  // placate compiler
        int axis = tid >> 5, c = tid & 31;
        const float* p = lines + axis * LTAB * CL + c;
        float s = 0.0f;
#pragma unroll 8
        for (int r = 0; r < LTAB; r++) s += p[r * CL];
        sMean[tid] = s * (1.0f / LTAB);
        (void)col;
    }
    __syncthreads();

    // ---- fbar_c = polynomial of per-axis means (axes independent) ----
    if (tid < CL) {
        float mx = sMean[tid], my = sMean[32 + tid], mz = sMean[64 + tid];
        float s  = mx + my + mz;
        float p2 = mx * my + mx * mz + my * mz;
        float p3 = mx * my * mz;
        float fb = fmaf(p3, 6.25f, fmaf(p2, 2.5f, s));
        sFBn[tid] = fb;
        int q = (tid & 7) >> 1;
        int j = 2 * (tid >> 3) + (tid & 1);
        sFBp[q * 8 + j] = fb;   // quarter-permuted order (matches feats)
    }
    __syncthreads();

    // ---- fold sum_c fbar_c * W1[h,c] into b1 (fp32, exact scheme-wise) ----
    if (tid < HDIM) {
        const float4* wrow = reinterpret_cast<const float4*>(W1 + tid * CL);
        const float4* fb4  = reinterpret_cast<const float4*>(sFBn);
        float acc = b1[tid];
#pragma unroll
        for (int j = 0; j < 8; j++) {
            float4 w = wrow[j];
            float4 f = fb4[j];
            acc = fmaf(w.x, f.x, acc);
            acc = fmaf(w.y, f.y, acc);
            acc = fmaf(w.z, f.z, acc);
            acc = fmaf(w.w, f.w, acc);
        }
        sB1p[tid] = acc;
    }
    __syncthreads();
    // ---- stage packed (b1', b1'', W2, W2') per column pair ----
    if (tid < HDIM / 2) {
        sBW[tid] = make_float4(sB1p[2 * tid], sB1p[2 * tid + 1],
                               W2[2 * tid], W2[2 * tid + 1]);
    }
    __syncthreads();

    const float bias2 = __ldg(b2);
    const uint32_t b_addr_base =
        (sb + SM_W1) + (uint32_t)(lane & 7) * ROWPAD + (uint32_t)(lane >> 3) * 16;

    const int qoff = (lane & 3) * 8;
    const int base = lane >> 2;

    // lane's fbar pairs, resident for the whole kernel
    ull fb2[4];
    {
        const ull* fp = reinterpret_cast<const ull*>(sFBp + qoff);
        fb2[0] = fp[0]; fb2[1] = fp[1]; fb2[2] = fp[2]; fb2[3] = fp[3];
    }

    const int warp_gid    = blockIdx.x * WARPS_PER_CTA + wid;
    const int total_warps = NBLOCKS * WARPS_PER_CTA;
    const int tiles       = (M + TILE_M - 1) / TILE_M;

    for (int t = warp_gid; t < tiles; t += total_warps) {
        // ---- build centered fp16 A fragments: 4 points per lane ----
        uint32_t afh[2][2][4];   // [row-tile][k16-chunk][frag reg]
#pragma unroll
        for (int pi = 0; pi < 4; pi++) {
            int p  = t * TILE_M + base + pi * 8;
            int pc = (p < M) ? p : (M - 1);
            float cx = __ldg(&coords[3 * pc + 0]);
            float cy = __ldg(&coords[3 * pc + 1]);
            float cz = __ldg(&coords[3 * pc + 2]);
            uint32_t h[4];
            feats8_c(sT, qoff, cx, cy, cz, fb2, h);

            int rt = pi >> 1;
            int rs = pi & 1;
            afh[rt][0][rs]     = h[0];   // cols 2q,2q+1       (k chunk 0)
            afh[rt][0][2 + rs] = h[1];   // cols 2q+8,2q+9
            afh[rt][1][rs]     = h[2];   // cols 2q+16,2q+17   (k chunk 1)
            afh[rt][1][2 + rs] = h[3];   // cols 2q+24,2q+25
        }

        float oacc[4] = {0.f, 0.f, 0.f, 0.f};

#pragma unroll
        for (int np8 = 0; np8 < 16; np8++) {
            uint32_t bwh[4];  // [k0 lo, k0 hi, k1 lo, k1 hi] of 8 n-rows
            ldsm_x4(b_addr_base + (uint32_t)(np8 * 8) * ROWPAD, bwh);
            float4 bw = sBW[np8 * 4 + (lane & 3)];  // b1',b1'',W2,W2'

#pragma unroll
            for (int rt = 0; rt < 2; rt++) {
                float4 c = make_float4(bw.x, bw.y, bw.x, bw.y);  // folded bias
                mma_f16(c, afh[rt][0], &bwh[0]);   // f'*w k0
                mma_f16(c, afh[rt][1], &bwh[2]);   // f'*w k1
                oacc[2 * rt + 0] = fmaf(fmaxf(c.x, 0.f), bw.z, oacc[2 * rt + 0]);
                oacc[2 * rt + 0] = fmaf(fmaxf(c.y, 0.f), bw.w, oacc[2 * rt + 0]);
                oacc[2 * rt + 1] = fmaf(fmaxf(c.z, 0.f), bw.z, oacc[2 * rt + 1]);
                oacc[2 * rt + 1] = fmaf(fmaxf(c.w, 0.f), bw.w, oacc[2 * rt + 1]);
            }
        }

        // ---- reduce over the 4 lanes sharing each row, then store ----
#pragma unroll
        for (int i = 0; i < 4; i++) {
            oacc[i] += __shfl_xor_sync(0xffffffffu, oacc[i], 1);
            oacc[i] += __shfl_xor_sync(0xffffffffu, oacc[i], 2);
        }
        if ((lane & 3) == 0) {
            int pb = t * TILE_M + base;
            if (pb      < M) out[pb]      = oacc[0] + bias2;
            if (pb + 8  < M) out[pb + 8]  = oacc[1] + bias2;
            if (pb + 16 < M) out[pb + 16] = oacc[2] + bias2;
            if (pb + 24 < M) out[pb + 24] = oacc[3] + bias2;
        }
    }
}

extern "C" void kernel_launch(void* const* d_in, const int* in_sizes, int n_in,
                              void* d_out, int out_size) {
    const float* coords = (const float*)d_in[0];
    const float* lines  = (const float*)d_in[1];
    const float* W1     = (const float*)d_in[2];
    const float* b1     = (const float*)d_in[3];
    const float* W2     = (const float*)d_in[4];
    const float* b2     = (const float*)d_in[5];
    float* out = (float*)d_out;

    int M = in_sizes[0] / 3;

    cudaFuncSetAttribute(rank1_hmma_kernel,
                         cudaFuncAttributeMaxDynamicSharedMemorySize, SMEM_BYTES);

    rank1_hmma_kernel<<<NBLOCKS, NTHREADS, SMEM_BYTES>>>(
        coords, lines, W1, b1, W2, b2, out, M);
}

// round 15
// speedup vs baseline: 1.5439x; 1.0169x over previous
#include <cuda_runtime.h>
#include <cuda_fp16.h>
#include <cstdint>

// RankOnePlanes, round 15: R14's centered-feature scheme (measured
// rel_err 2.74e-4), streamlined:
//  - constant FBAR instead of per-channel means (channel means are
//    0.3 +/- 0.01 vs residual sigma 0.53 -> identical residual), deleting
//    the mean-staging loops, two syncs, and fbar smem loads;
//  - bias fold b1' = b1 + FBAR * sum_c W1[h,c] in fp32, computed directly
//    into the packed (b1',b1'',W2,W2') float4;
//  - TILE_M 64: LDSM + epilogue-constant loads halved per point
//    (R10-validated shape; fits the (256,3) 85-reg cap without afl).

#define LTAB 128
#define CL 32
#define HDIM 128
#define TSTRIDE 36   // floats per table row (4 x 32B quarter-blocks + 16B pad)
#define NTHREADS 256
#define WARPS_PER_CTA 8
#define NBLOCKS 456  // 3 per SM
#define ROWPAD 80    // W1 fp16 row bytes: 64B data + 16B pad
#define TILE_M 64
#define FBAR 1.74375f

// ---- smem byte offsets ----
#define SM_TAB  0                         // 3*128*36*4 = 55296
#define SM_W1   55296                     // 128 * 80   = 10240
#define SM_BW   65536                     // 64 float4  = 1024
#define SMEM_BYTES 66560                  // x3 CTAs = 199.7 KB/SM

typedef unsigned long long ull;

__device__ __forceinline__ uint32_t smem_u32(const void* p) {
    uint32_t a;
    asm("{ .reg .u64 t; cvta.to.shared.u64 t, %1; cvt.u32.u64 %0, t; }"
        : "=r"(a) : "l"(p));
    return a;
}
__device__ __forceinline__ void ldsm_x4(uint32_t addr, uint32_t* r) {
    asm volatile("ldmatrix.sync.aligned.m8n8.x4.shared.b16 {%0,%1,%2,%3}, [%4];"
                 : "=r"(r[0]), "=r"(r[1]), "=r"(r[2]), "=r"(r[3]) : "r"(addr));
}
__device__ __forceinline__ void mma_f16(float4& c, const uint32_t* a,
                                        const uint32_t* b) {
    asm volatile(
        "mma.sync.aligned.m16n8k16.row.col.f32.f16.f16.f32 "
        "{%0,%1,%2,%3}, {%4,%5,%6,%7}, {%8,%9}, {%0,%1,%2,%3};"
        : "+f"(c.x), "+f"(c.y), "+f"(c.z), "+f"(c.w)
        : "r"(a[0]), "r"(a[1]), "r"(a[2]), "r"(a[3]), "r"(b[0]), "r"(b[1]));
}
// pack (lo, hi) floats -> f16x2 (lo in low half)
__device__ __forceinline__ uint32_t pkh(float lo, float hi) {
    uint32_t r;
    asm("cvt.rn.f16x2.f32 %0, %1, %2;" : "=r"(r) : "f"(hi), "f"(lo));
    return r;
}
// ---- f32x2 packed helpers ----
__device__ __forceinline__ ull pk2(float lo, float hi) {
    ull r;
    asm("mov.b64 %0, {%1, %2};" : "=l"(r) : "f"(lo), "f"(hi));
    return r;
}
__device__ __forceinline__ void unpk2(float& lo, float& hi, ull v) {
    asm("mov.b64 {%0, %1}, %2;" : "=f"(lo), "=f"(hi) : "l"(v));
}
__device__ __forceinline__ ull mul2(ull a, ull b) {
    ull d;
    asm("mul.rn.f32x2 %0, %1, %2;" : "=l"(d) : "l"(a), "l"(b));
    return d;
}
__device__ __forceinline__ ull add2(ull a, ull b) {
    ull d;
    asm("add.rn.f32x2 %0, %1, %2;" : "=l"(d) : "l"(a), "l"(b));
    return d;
}
__device__ __forceinline__ ull sub2(ull a, ull b) {
    ull d;
    asm("sub.rn.f32x2 %0, %1, %2;" : "=l"(d) : "l"(a), "l"(b));
    return d;
}
__device__ __forceinline__ ull fma2(ull a, ull b, ull c) {
    ull d;
    asm("fma.rn.f32x2 %0, %1, %2, %3;" : "=l"(d) : "l"(a), "l"(b), "l"(c));
    return d;
}

__device__ __forceinline__ void sample_setup(float c, int& r0, int& r1,
                                             float& w0, float& w1) {
    float pos = (c + 1.0f) * 63.5f;
    float f0  = floorf(pos);
    float fr  = pos - f0;
    int i0 = (int)f0;
    int i1 = i0 + 1;
    w0 = ((unsigned)i0 < (unsigned)LTAB) ? (1.0f - fr) : 0.0f;
    w1 = ((unsigned)i1 < (unsigned)LTAB) ? fr : 0.0f;
    r0 = min(max(i0, 0), LTAB - 1);
    r1 = min(max(i1, 0), LTAB - 1);
}

// 8 centered features of one point (this lane's quarter-block channels),
// f32x2 math; emits 4 f16x2 fragment registers of (f - FBAR).
__device__ __forceinline__ void feats8_c(const float* __restrict__ sT, int qoff,
                                         float cx, float cy, float cz,
                                         uint32_t* __restrict__ hreg) {
    int xr0, xr1, yr0, yr1, zr0, zr1;
    float xw0, xw1, yw0, yw1, zw0, zw1;
    sample_setup(cx, xr0, xr1, xw0, xw1);
    sample_setup(cy, yr0, yr1, yw0, yw1);
    sample_setup(cz, zr0, zr1, zw0, zw1);

    const ulonglong2* X0 = reinterpret_cast<const ulonglong2*>(&sT[(0 * LTAB + xr0) * TSTRIDE + qoff]);
    const ulonglong2* X1 = reinterpret_cast<const ulonglong2*>(&sT[(0 * LTAB + xr1) * TSTRIDE + qoff]);
    const ulonglong2* Y0 = reinterpret_cast<const ulonglong2*>(&sT[(1 * LTAB + yr0) * TSTRIDE + qoff]);
    const ulonglong2* Y1 = reinterpret_cast<const ulonglong2*>(&sT[(1 * LTAB + yr1) * TSTRIDE + qoff]);
    const ulonglong2* Z0 = reinterpret_cast<const ulonglong2*>(&sT[(2 * LTAB + zr0) * TSTRIDE + qoff]);
    const ulonglong2* Z1 = reinterpret_cast<const ulonglong2*>(&sT[(2 * LTAB + zr1) * TSTRIDE + qoff]);

    const ull xw0p = pk2(xw0, xw0), xw1p = pk2(xw1, xw1);
    const ull yw0p = pk2(yw0, yw0), yw1p = pk2(yw1, yw1);
    const ull zw0p = pk2(zw0, zw0), zw1p = pk2(zw1, zw1);
    const ull invRp  = 0x4020000040200000ull;  // {2.5f, 2.5f}
    const ull invR2p = 0x40C8000040C80000ull;  // {6.25f, 6.25f}
    const ull fbarp  = 0x3FDF40003FDF4000ull;  // {1.74375f, 1.74375f}

    ulonglong2 x0 = X0[0], x0b = X0[1];
    ulonglong2 x1 = X1[0], x1b = X1[1];
    ulonglong2 y0 = Y0[0], y0b = Y0[1];
    ulonglong2 y1 = Y1[0], y1b = Y1[1];
    ulonglong2 z0 = Z0[0], z0b = Z0[1];
    ulonglong2 z1 = Z1[0], z1b = Z1[1];

    ull xp[4] = {x0.x, x0.y, x0b.x, x0b.y};
    ull xq[4] = {x1.x, x1.y, x1b.x, x1b.y};
    ull yp[4] = {y0.x, y0.y, y0b.x, y0b.y};
    ull yq[4] = {y1.x, y1.y, y1b.x, y1b.y};
    ull zp[4] = {z0.x, z0.y, z0b.x, z0b.y};
    ull zq[4] = {z1.x, z1.y, z1b.x, z1b.y};

#pragma unroll
    for (int pr = 0; pr < 4; pr++) {
        ull xv = fma2(xq[pr], xw1p, mul2(xp[pr], xw0p));
        ull yv = fma2(yq[pr], yw1p, mul2(yp[pr], yw0p));
        ull zv = fma2(zq[pr], zw1p, mul2(zp[pr], zw0p));
        ull e  = add2(xv, yv);
        ull s  = add2(e, zv);
        ull xy = mul2(xv, yv);
        ull p2 = fma2(zv, e, xy);
        ull p3 = mul2(xy, zv);
        ull f  = fma2(p2, invRp, s);
        f = fma2(p3, invR2p, f);
        f = sub2(f, fbarp);          // center: f' = f - FBAR
        float a0, a1;
        unpk2(a0, a1, f);
        hreg[pr] = pkh(a0, a1);
    }
}

__global__ __launch_bounds__(NTHREADS, 3)
void rank1_hmma_kernel(const float* __restrict__ coords,
                       const float* __restrict__ lines,
                       const float* __restrict__ W1,
                       const float* __restrict__ b1,
                       const float* __restrict__ W2,
                       const float* __restrict__ b2,
                       float* __restrict__ out, int M) {
    extern __shared__ char smc[];
    float* sT   = reinterpret_cast<float*>(smc + SM_TAB);
    float4* sBW = reinterpret_cast<float4*>(smc + SM_BW);
    const uint32_t sb = smem_u32(smc);

    const int tid  = threadIdx.x;
    const int wid  = tid >> 5;
    const int lane = tid & 31;

    // ---- stage table: per row, 4 quarter-blocks of 8 permuted channels ----
    // block q holds channels {2q,2q+1,2q+8,2q+9,2q+16,2q+17,2q+24,2q+25}
    for (int idx = tid; idx < 3 * LTAB; idx += NTHREADS) {
        const float* src = lines + idx * CL;
        float v[CL];
#pragma unroll
        for (int j = 0; j < 8; j++) {
            float4 t4 = reinterpret_cast<const float4*>(src)[j];
            v[4 * j + 0] = t4.x; v[4 * j + 1] = t4.y;
            v[4 * j + 2] = t4.z; v[4 * j + 3] = t4.w;
        }
        float* dst = sT + idx * TSTRIDE;
#pragma unroll
        for (int q = 0; q < 4; q++) {
            dst[8 * q + 0] = v[2 * q];      dst[8 * q + 1] = v[2 * q + 1];
            dst[8 * q + 2] = v[2 * q + 8];  dst[8 * q + 3] = v[2 * q + 9];
            dst[8 * q + 4] = v[2 * q + 16]; dst[8 * q + 5] = v[2 * q + 17];
            dst[8 * q + 6] = v[2 * q + 24]; dst[8 * q + 7] = v[2 * q + 25];
        }
    }
    // ---- stage fp16 W1 rows (rn) ----
    if (tid < HDIM) {
        char* dst = smc + SM_W1 + tid * ROWPAD;
        const float4* wrow = reinterpret_cast<const float4*>(W1 + tid * CL);
#pragma unroll
        for (int j = 0; j < 8; j += 2) {
            float4 wa = wrow[j], wb = wrow[j + 1];
            *reinterpret_cast<uint4*>(dst + j * 8) =
                make_uint4(pkh(wa.x, wa.y), pkh(wa.z, wa.w),
                           pkh(wb.x, wb.y), pkh(wb.z, wb.w));
        }
    }
    // ---- stage packed (b1', b1'', W2, W2') with FBAR row-sum fold ----
    if (tid < HDIM / 2) {
        float acc[2];
#pragma unroll
        for (int k = 0; k < 2; k++) {
            int h = 2 * tid + k;
            const float4* wrow = reinterpret_cast<const float4*>(W1 + h * CL);
            float s = 0.0f;
#pragma unroll
            for (int j = 0; j < 8; j++) {
                float4 w = wrow[j];
                s += (w.x + w.y) + (w.z + w.w);
            }
            acc[k] = fmaf(FBAR, s, b1[h]);
        }
        sBW[tid] = make_float4(acc[0], acc[1], W2[2 * tid], W2[2 * tid + 1]);
    }
    __syncthreads();

    const float bias2 = __ldg(b2);
    const uint32_t b_addr_base =
        (sb + SM_W1) + (uint32_t)(lane & 7) * ROWPAD + (uint32_t)(lane >> 3) * 16;

    const int qoff = (lane & 3) * 8;
    const int base = lane >> 2;

    const int warp_gid    = blockIdx.x * WARPS_PER_CTA + wid;
    const int total_warps = NBLOCKS * WARPS_PER_CTA;
    const int tiles       = (M + TILE_M - 1) / TILE_M;

    for (int t = warp_gid; t < tiles; t += total_warps) {
        // ---- build centered fp16 A fragments: 8 points per lane ----
        uint32_t afh[4][2][4];   // [row-tile][k16-chunk][frag reg]
#pragma unroll
        for (int pi = 0; pi < 8; pi++) {
            int p  = t * TILE_M + base + pi * 8;
            int pc = (p < M) ? p : (M - 1);
            float cx = __ldg(&coords[3 * pc + 0]);
            float cy = __ldg(&coords[3 * pc + 1]);
            float cz = __ldg(&coords[3 * pc + 2]);
            uint32_t h[4];
            feats8_c(sT, qoff, cx, cy, cz, h);

            int rt = pi >> 1;
            int rs = pi & 1;
            afh[rt][0][rs]     = h[0];   // cols 2q,2q+1       (k chunk 0)
            afh[rt][0][2 + rs] = h[1];   // cols 2q+8,2q+9
            afh[rt][1][rs]     = h[2];   // cols 2q+16,2q+17   (k chunk 1)
            afh[rt][1][2 + rs] = h[3];   // cols 2q+24,2q+25
        }

        float oacc[8];
#pragma unroll
        for (int i = 0; i < 8; i++) oacc[i] = 0.0f;

#pragma unroll
        for (int np8 = 0; np8 < 16; np8++) {
            uint32_t bwh[4];  // [k0 lo, k0 hi, k1 lo, k1 hi] of 8 n-rows
            ldsm_x4(b_addr_base + (uint32_t)(np8 * 8) * ROWPAD, bwh);
            float4 bw = sBW[np8 * 4 + (lane & 3)];  // b1',b1'',W2,W2'

#pragma unroll
            for (int rt = 0; rt < 4; rt++) {
                float4 c = make_float4(bw.x, bw.y, bw.x, bw.y);  // folded bias
                mma_f16(c, afh[rt][0], &bwh[0]);   // f'*w k0
                mma_f16(c, afh[rt][1], &bwh[2]);   // f'*w k1
                oacc[2 * rt + 0] = fmaf(fmaxf(c.x, 0.f), bw.z, oacc[2 * rt + 0]);
                oacc[2 * rt + 0] = fmaf(fmaxf(c.y, 0.f), bw.w, oacc[2 * rt + 0]);
                oacc[2 * rt + 1] = fmaf(fmaxf(c.z, 0.f), bw.z, oacc[2 * rt + 1]);
                oacc[2 * rt + 1] = fmaf(fmaxf(c.w, 0.f), bw.w, oacc[2 * rt + 1]);
            }
        }

        // ---- reduce over the 4 lanes sharing each row, then store ----
#pragma unroll
        for (int i = 0; i < 8; i++) {
            oacc[i] += __shfl_xor_sync(0xffffffffu, oacc[i], 1);
            oacc[i] += __shfl_xor_sync(0xffffffffu, oacc[i], 2);
        }
        if ((lane & 3) == 0) {
            int pb = t * TILE_M + base;
#pragma unroll
            for (int rt = 0; rt < 4; rt++) {
                int p0 = pb + rt * 16;
                if (p0     < M) out[p0]     = oacc[2 * rt + 0] + bias2;
                if (p0 + 8 < M) out[p0 + 8] = oacc[2 * rt + 1] + bias2;
            }
        }
    }
}

extern "C" void kernel_launch(void* const* d_in, const int* in_sizes, int n_in,
                              void* d_out, int out_size) {
    const float* coords = (const float*)d_in[0];
    const float* lines  = (const float*)d_in[1];
    const float* W1     = (const float*)d_in[2];
    const float* b1     = (const float*)d_in[3];
    const float* W2     = (const float*)d_in[4];
    const float* b2     = (const float*)d_in[5];
    float* out = (float*)d_out;

    int M = in_sizes[0] / 3;

    cudaFuncSetAttribute(rank1_hmma_kernel,
                         cudaFuncAttributeMaxDynamicSharedMemorySize, SMEM_BYTES);

    rank1_hmma_kernel<<<NBLOCKS, NTHREADS, SMEM_BYTES>>>(
        coords, lines, W1, b1, W2, b2, out, M);
}

// round 16
// speedup vs baseline: 1.6778x; 1.0867x over previous
#include <cuda_runtime.h>
#include <cuda_fp16.h>
#include <cstdint>

// RankOnePlanes, round 16: R8's fastest-measured chassis (TILE32, np-loop,
// (256,3)) + the calibrated centering scheme (rel_err ~3e-4, 3x gate
// margin) + feat-path slimming:
//  - OOB masks deleted (pos in [0,127] always for coords in [-1,1];
//    float-clamp i0 to [0,126], frac=pos-i0 handles the pos=127 edge)
//  - lerp bilinear (x0 + fr*(x1-x0)): no w0/w1 packs
//  - tap-1 row = tap-0 row + 36 floats: 3 address IMADs, not 6.

#define LTAB 128
#define CL 32
#define HDIM 128
#define TSTRIDE 36   // floats per table row (4 x 32B quarter-blocks + 16B pad)
#define NTHREADS 256
#define WARPS_PER_CTA 8
#define NBLOCKS 456  // 3 per SM
#define ROWPAD 80    // W1 fp16 row bytes (64B data + 16B pad)
#define FBAR 1.74375f

// ---- smem byte offsets ----
#define SM_TAB 0                          // 3*128*36*4 = 55296
#define SM_W1  55296                      // 128 * 80   = 10240
#define SM_B1  65536                      // 512
#define SM_W2  66048                      // 512
#define SMEM_BYTES 66560                  // x3 CTAs = 199.7 KB/SM

typedef unsigned long long ull;

__device__ __forceinline__ uint32_t smem_u32(const void* p) {
    uint32_t a;
    asm("{ .reg .u64 t; cvta.to.shared.u64 t, %1; cvt.u32.u64 %0, t; }"
        : "=r"(a) : "l"(p));
    return a;
}
__device__ __forceinline__ void ldsm_x4(uint32_t addr, uint32_t* r) {
    asm volatile("ldmatrix.sync.aligned.m8n8.x4.shared.b16 {%0,%1,%2,%3}, [%4];"
                 : "=r"(r[0]), "=r"(r[1]), "=r"(r[2]), "=r"(r[3]) : "r"(addr));
}
__device__ __forceinline__ void mma_f16(float4& c, const uint32_t* a,
                                        const uint32_t* b) {
    asm volatile(
        "mma.sync.aligned.m16n8k16.row.col.f32.f16.f16.f32 "
        "{%0,%1,%2,%3}, {%4,%5,%6,%7}, {%8,%9}, {%0,%1,%2,%3};"
        : "+f"(c.x), "+f"(c.y), "+f"(c.z), "+f"(c.w)
        : "r"(a[0]), "r"(a[1]), "r"(a[2]), "r"(a[3]), "r"(b[0]), "r"(b[1]));
}
// pack (lo, hi) floats -> f16x2 (lo in low half)
__device__ __forceinline__ uint32_t pkh(float lo, float hi) {
    uint32_t r;
    asm("cvt.rn.f16x2.f32 %0, %1, %2;" : "=r"(r) : "f"(hi), "f"(lo));
    return r;
}
// ---- f32x2 packed helpers ----
__device__ __forceinline__ ull pk2(float lo, float hi) {
    ull r;
    asm("mov.b64 %0, {%1, %2};" : "=l"(r) : "f"(lo), "f"(hi));
    return r;
}
__device__ __forceinline__ void unpk2(float& lo, float& hi, ull v) {
    asm("mov.b64 {%0, %1}, %2;" : "=f"(lo), "=f"(hi) : "l"(v));
}
__device__ __forceinline__ ull mul2(ull a, ull b) {
    ull d;
    asm("mul.rn.f32x2 %0, %1, %2;" : "=l"(d) : "l"(a), "l"(b));
    return d;
}
__device__ __forceinline__ ull add2(ull a, ull b) {
    ull d;
    asm("add.rn.f32x2 %0, %1, %2;" : "=l"(d) : "l"(a), "l"(b));
    return d;
}
__device__ __forceinline__ ull sub2(ull a, ull b) {
    ull d;
    asm("sub.rn.f32x2 %0, %1, %2;" : "=l"(d) : "l"(a), "l"(b));
    return d;
}
__device__ __forceinline__ ull fma2(ull a, ull b, ull c) {
    ull d;
    asm("fma.rn.f32x2 %0, %1, %2, %3;" : "=l"(d) : "l"(a), "l"(b), "l"(c));
    return d;
}

// Slim setup: no OOB masks (pos in [0,127] for c in [-1,1]); float clamp
// handles pos=127 (i0=126, frac=1 -> samples row 127 exactly).
__device__ __forceinline__ void setup_slim(float c, int& i0, float& fr) {
    float pos = fmaf(c, 63.5f, 63.5f);
    float f0  = floorf(pos);
    f0 = fminf(fmaxf(f0, 0.0f), 126.0f);
    i0 = (int)f0;
    fr = pos - f0;
}

// 8 centered features of one point (this lane's quarter-block channels):
// lerp bilinear in f32x2, polynomial, center by FBAR, emit 4 f16x2 regs.
__device__ __forceinline__ void feats8_c(const float* __restrict__ sT, int qoff,
                                         float cx, float cy, float cz,
                                         uint32_t* __restrict__ hreg) {
    int xi, yi, zi;
    float frx, fry, frz;
    setup_slim(cx, xi, frx);
    setup_slim(cy, yi, fry);
    setup_slim(cz, zi, frz);

    const ulonglong2* X0 = reinterpret_cast<const ulonglong2*>(&sT[(0 * LTAB + xi) * TSTRIDE + qoff]);
    const ulonglong2* Y0 = reinterpret_cast<const ulonglong2*>(&sT[(1 * LTAB + yi) * TSTRIDE + qoff]);
    const ulonglong2* Z0 = reinterpret_cast<const ulonglong2*>(&sT[(2 * LTAB + zi) * TSTRIDE + qoff]);
    // tap 1 = tap 0 + one row = +36 floats = +9 ulonglong2

    const ull frxp = pk2(frx, frx);
    const ull fryp = pk2(fry, fry);
    const ull frzp = pk2(frz, frz);
    const ull invRp  = 0x4020000040200000ull;  // {2.5f, 2.5f}
    const ull invR2p = 0x40C8000040C80000ull;  // {6.25f, 6.25f}
    const ull fbarp  = 0x3FDF40003FDF4000ull;  // {1.74375f, 1.74375f}

    ulonglong2 xa = X0[0], xb = X0[1], xc = X0[9], xd = X0[10];
    ulonglong2 ya = Y0[0], yb = Y0[1], yc = Y0[9], yd = Y0[10];
    ulonglong2 za = Z0[0], zb = Z0[1], zc = Z0[9], zd = Z0[10];

    ull xp[4] = {xa.x, xa.y, xb.x, xb.y};
    ull xq[4] = {xc.x, xc.y, xd.x, xd.y};
    ull yp[4] = {ya.x, ya.y, yb.x, yb.y};
    ull yq[4] = {yc.x, yc.y, yd.x, yd.y};
    ull zp[4] = {za.x, za.y, zb.x, zb.y};
    ull zq[4] = {zc.x, zc.y, zd.x, zd.y};

#pragma unroll
    for (int pr = 0; pr < 4; pr++) {
        ull xv = fma2(frxp, sub2(xq[pr], xp[pr]), xp[pr]);
        ull yv = fma2(fryp, sub2(yq[pr], yp[pr]), yp[pr]);
        ull zv = fma2(frzp, sub2(zq[pr], zp[pr]), zp[pr]);
        ull e  = add2(xv, yv);
        ull s  = add2(e, zv);
        ull xy = mul2(xv, yv);
        ull p2 = fma2(zv, e, xy);
        ull p3 = mul2(xy, zv);
        ull f  = fma2(p2, invRp, s);
        f = fma2(p3, invR2p, f);
        f = sub2(f, fbarp);          // center: f' = f - FBAR
        float a0, a1;
        unpk2(a0, a1, f);
        hreg[pr] = pkh(a0, a1);
    }
}

__global__ __launch_bounds__(NTHREADS, 3)
void rank1_hmma_kernel(const float* __restrict__ coords,
                       const float* __restrict__ lines,
                       const float* __restrict__ W1,
                       const float* __restrict__ b1,
                       const float* __restrict__ W2,
                       const float* __restrict__ b2,
                       float* __restrict__ out, int M) {
    extern __shared__ char smc[];
    const uint32_t sb = smem_u32(smc);
    float* sT  = reinterpret_cast<float*>(smc + SM_TAB);
    float* sb1 = reinterpret_cast<float*>(smc + SM_B1);
    float* sW2 = reinterpret_cast<float*>(smc + SM_W2);

    const int tid  = threadIdx.x;
    const int wid  = tid >> 5;
    const int lane = tid & 31;

    // ---- stage table: per row, 4 quarter-blocks of 8 permuted channels ----
    // block q holds channels {2q,2q+1,2q+8,2q+9,2q+16,2q+17,2q+24,2q+25}
    for (int idx = tid; idx < 3 * LTAB; idx += NTHREADS) {
        const float* src = lines + idx * CL;
        float v[CL];
#pragma unroll
        for (int j = 0; j < 8; j++) {
            float4 t4 = reinterpret_cast<const float4*>(src)[j];
            v[4 * j + 0] = t4.x; v[4 * j + 1] = t4.y;
            v[4 * j + 2] = t4.z; v[4 * j + 3] = t4.w;
        }
        float* dst = sT + idx * TSTRIDE;
#pragma unroll
        for (int q = 0; q < 4; q++) {
            dst[8 * q + 0] = v[2 * q];      dst[8 * q + 1] = v[2 * q + 1];
            dst[8 * q + 2] = v[2 * q + 8];  dst[8 * q + 3] = v[2 * q + 9];
            dst[8 * q + 4] = v[2 * q + 16]; dst[8 * q + 5] = v[2 * q + 17];
            dst[8 * q + 6] = v[2 * q + 24]; dst[8 * q + 7] = v[2 * q + 25];
        }
    }
    // ---- stage fp16 W1, folded b1' = b1 + FBAR*sum_c W1[h,c], and W2 ----
    if (tid < HDIM) {
        char* dst = smc + SM_W1 + tid * ROWPAD;
        const float4* wrow = reinterpret_cast<const float4*>(W1 + tid * CL);
        float s = 0.0f;
#pragma unroll
        for (int j = 0; j < 8; j += 2) {
            float4 wa = wrow[j], wb = wrow[j + 1];
            s += (wa.x + wa.y) + (wa.z + wa.w);
            s += (wb.x + wb.y) + (wb.z + wb.w);
            uint4 vh = make_uint4(pkh(wa.x, wa.y), pkh(wa.z, wa.w),
                                  pkh(wb.x, wb.y), pkh(wb.z, wb.w));
            *reinterpret_cast<uint4*>(dst + j * 8) = vh;
        }
        sb1[tid] = fmaf(FBAR, s, b1[tid]);
        sW2[tid] = W2[tid];
    }
    __syncthreads();

    const float bias2 = __ldg(b2);
    const uint32_t sbW1 = sb + SM_W1;

    // B ldmatrix addressing: 16 rows (2 n-tiles) x k16-chunk columns
    const uint32_t b_row = (uint32_t)((lane & 7) + ((lane & 16) ? 8 : 0));
    const uint32_t b_addr_base =
        sbW1 + b_row * ROWPAD + (uint32_t)((lane & 8) ? 16 : 0);

    const int qoff = (lane & 3) * 8;
    const int base = lane >> 2;

    const int warp_gid    = blockIdx.x * WARPS_PER_CTA + wid;
    const int total_warps = NBLOCKS * WARPS_PER_CTA;
    const int tiles       = (M + 31) >> 5;

    for (int t = warp_gid; t < tiles; t += total_warps) {
        // ---- build centered fp16 A fragments: 4 points per lane ----
        uint32_t afr[2][2][4];   // [row-tile][k16-chunk][frag reg]
#pragma unroll
        for (int pi = 0; pi < 4; pi++) {
            int prow = base + pi * 8;
            int p  = t * 32 + prow;
            int pc = (p < M) ? p : (M - 1);
            float cx = __ldg(&coords[3 * pc + 0]);
            float cy = __ldg(&coords[3 * pc + 1]);
            float cz = __ldg(&coords[3 * pc + 2]);
            uint32_t h[4];
            feats8_c(sT, qoff, cx, cy, cz, h);

            int rt = pi >> 1;
            int rs = pi & 1;
            afr[rt][0][rs]     = h[0];   // cols 2q,2q+1       (k chunk 0)
            afr[rt][0][2 + rs] = h[1];   // cols 2q+8,2q+9
            afr[rt][1][rs]     = h[2];   // cols 2q+16,2q+17   (k chunk 1)
            afr[rt][1][2 + rs] = h[3];   // cols 2q+24,2q+25
        }

        float oacc0 = 0.0f, oacc1 = 0.0f, oacc2 = 0.0f, oacc3 = 0.0f;
        const int colb = (lane & 3) * 2;

#pragma unroll
        for (int np = 0; np < 8; np++) {
            uint32_t b[2][4];  // [k16 chunk][ntile0 b0,b1, ntile1 b0,b1]
            uint32_t nb = b_addr_base + (uint32_t)(np * 16) * ROWPAD;
            ldsm_x4(nb,      b[0]);
            ldsm_x4(nb + 32, b[1]);

            float4 c[2][2];
#pragma unroll
            for (int rt = 0; rt < 2; rt++)
#pragma unroll
                for (int nt = 0; nt < 2; nt++) {
                    c[rt][nt] = make_float4(0.f, 0.f, 0.f, 0.f);
                    mma_f16(c[rt][nt], afr[rt][0], &b[0][nt * 2]);
                    mma_f16(c[rt][nt], afr[rt][1], &b[1][nt * 2]);
                }

            // ---- fused epilogue on fragments (folded b1') ----
            int col0 = np * 16 + colb;
            float2 b1a = *reinterpret_cast<const float2*>(&sb1[col0]);
            float2 w2a = *reinterpret_cast<const float2*>(&sW2[col0]);
            float2 b1b = *reinterpret_cast<const float2*>(&sb1[col0 + 8]);
            float2 w2b = *reinterpret_cast<const float2*>(&sW2[col0 + 8]);
#pragma unroll
            for (int rt = 0; rt < 2; rt++) {
                float lo = 0.0f, hi = 0.0f;
                lo = fmaf(fmaxf(c[rt][0].x + b1a.x, 0.f), w2a.x, lo);
                lo = fmaf(fmaxf(c[rt][0].y + b1a.y, 0.f), w2a.y, lo);
                lo = fmaf(fmaxf(c[rt][1].x + b1b.x, 0.f), w2b.x, lo);
                lo = fmaf(fmaxf(c[rt][1].y + b1b.y, 0.f), w2b.y, lo);
                hi = fmaf(fmaxf(c[rt][0].z + b1a.x, 0.f), w2a.x, hi);
                hi = fmaf(fmaxf(c[rt][0].w + b1a.y, 0.f), w2a.y, hi);
                hi = fmaf(fmaxf(c[rt][1].z + b1b.x, 0.f), w2b.x, hi);
                hi = fmaf(fmaxf(c[rt][1].w + b1b.y, 0.f), w2b.y, hi);
                if (rt == 0) { oacc0 += lo; oacc1 += hi; }
                else         { oacc2 += lo; oacc3 += hi; }
            }
        }

        // ---- reduce over the 4 lanes sharing each row ----
        oacc0 += __shfl_xor_sync(0xffffffffu, oacc0, 1);
        oacc0 += __shfl_xor_sync(0xffffffffu, oacc0, 2);
        oacc1 += __shfl_xor_sync(0xffffffffu, oacc1, 1);
        oacc1 += __shfl_xor_sync(0xffffffffu, oacc1, 2);
        oacc2 += __shfl_xor_sync(0xffffffffu, oacc2, 1);
        oacc2 += __shfl_xor_sync(0xffffffffu, oacc2, 2);
        oacc3 += __shfl_xor_sync(0xffffffffu, oacc3, 1);
        oacc3 += __shfl_xor_sync(0xffffffffu, oacc3, 2);

        if ((lane & 3) == 0) {
            int r  = lane >> 2;
            int pb = t * 32;
            if (pb + r      < M) out[pb + r]      = oacc0 + bias2;
            if (pb + r + 8  < M) out[pb + r + 8]  = oacc1 + bias2;
            if (pb + r + 16 < M) out[pb + r + 16] = oacc2 + bias2;
            if (pb + r + 24 < M) out[pb + r + 24] = oacc3 + bias2;
        }
    }
}

extern "C" void kernel_launch(void* const* d_in, const int* in_sizes, int n_in,
                              void* d_out, int out_size) {
    const float* coords = (const float*)d_in[0];
    const float* lines  = (const float*)d_in[1];
    const float* W1     = (const float*)d_in[2];
    const float* b1     = (const float*)d_in[3];
    const float* W2     = (const float*)d_in[4];
    const float* b2     = (const float*)d_in[5];
    float* out = (float*)d_out;

    int M = in_sizes[0] / 3;

    cudaFuncSetAttribute(rank1_hmma_kernel,
                         cudaFuncAttributeMaxDynamicSharedMemorySize, SMEM_BYTES);

    rank1_hmma_kernel<<<NBLOCKS, NTHREADS, SMEM_BYTES>>>(
        coords, lines, W1, b1, W2, b2, out, M);
}

// round 17
// speedup vs baseline: 1.7009x; 1.0138x over previous
#include <cuda_runtime.h>
#include <cuda_fp16.h>
#include <cstdint>

// RankOnePlanes, round 17: R16 (66.0us, rel_err 3.09e-4, L1-bound 83%)
// with the two remaining non-table L1 cuts compounded:
//  - TILE_M 64 via R15's np8 mainloop: 1 ldmatrix.x4 per 8-column step
//    (full k32 B for 8 n-rows), LDSM phases halved per point;
//  - (b1,b1',W2,W2') float4: 1 LDS.128 per step for epilogue constants;
//  - bias folded into MMA accumulator init;
//  - R16's slim feat path kept verbatim (lerp, no OOB masks, +9-row tap).
// Math identical to R16's calibrated centering scheme.

#define LTAB 128
#define CL 32
#define HDIM 128
#define TSTRIDE 36   // floats per table row (4 x 32B quarter-blocks + 16B pad)
#define NTHREADS 256
#define WARPS_PER_CTA 8
#define NBLOCKS 456  // 3 per SM
#define ROWPAD 80    // W1 fp16 row bytes (64B data + 16B pad)
#define TILE_M 64
#define FBAR 1.74375f

// ---- smem byte offsets ----
#define SM_TAB 0                          // 3*128*36*4 = 55296
#define SM_W1  55296                      // 128 * 80   = 10240
#define SM_BW  65536                      // 64 float4  = 1024
#define SMEM_BYTES 66560                  // x3 CTAs = 199.7 KB/SM

typedef unsigned long long ull;

__device__ __forceinline__ uint32_t smem_u32(const void* p) {
    uint32_t a;
    asm("{ .reg .u64 t; cvta.to.shared.u64 t, %1; cvt.u32.u64 %0, t; }"
        : "=r"(a) : "l"(p));
    return a;
}
__device__ __forceinline__ void ldsm_x4(uint32_t addr, uint32_t* r) {
    asm volatile("ldmatrix.sync.aligned.m8n8.x4.shared.b16 {%0,%1,%2,%3}, [%4];"
                 : "=r"(r[0]), "=r"(r[1]), "=r"(r[2]), "=r"(r[3]) : "r"(addr));
}
__device__ __forceinline__ void mma_f16(float4& c, const uint32_t* a,
                                        const uint32_t* b) {
    asm volatile(
        "mma.sync.aligned.m16n8k16.row.col.f32.f16.f16.f32 "
        "{%0,%1,%2,%3}, {%4,%5,%6,%7}, {%8,%9}, {%0,%1,%2,%3};"
        : "+f"(c.x), "+f"(c.y), "+f"(c.z), "+f"(c.w)
        : "r"(a[0]), "r"(a[1]), "r"(a[2]), "r"(a[3]), "r"(b[0]), "r"(b[1]));
}
// pack (lo, hi) floats -> f16x2 (lo in low half)
__device__ __forceinline__ uint32_t pkh(float lo, float hi) {
    uint32_t r;
    asm("cvt.rn.f16x2.f32 %0, %1, %2;" : "=r"(r) : "f"(hi), "f"(lo));
    return r;
}
// ---- f32x2 packed helpers ----
__device__ __forceinline__ ull pk2(float lo, float hi) {
    ull r;
    asm("mov.b64 %0, {%1, %2};" : "=l"(r) : "f"(lo), "f"(hi));
    return r;
}
__device__ __forceinline__ void unpk2(float& lo, float& hi, ull v) {
    asm("mov.b64 {%0, %1}, %2;" : "=f"(lo), "=f"(hi) : "l"(v));
}
__device__ __forceinline__ ull mul2(ull a, ull b) {
    ull d;
    asm("mul.rn.f32x2 %0, %1, %2;" : "=l"(d) : "l"(a), "l"(b));
    return d;
}
__device__ __forceinline__ ull add2(ull a, ull b) {
    ull d;
    asm("add.rn.f32x2 %0, %1, %2;" : "=l"(d) : "l"(a), "l"(b));
    return d;
}
__device__ __forceinline__ ull sub2(ull a, ull b) {
    ull d;
    asm("sub.rn.f32x2 %0, %1, %2;" : "=l"(d) : "l"(a), "l"(b));
    return d;
}
__device__ __forceinline__ ull fma2(ull a, ull b, ull c) {
    ull d;
    asm("fma.rn.f32x2 %0, %1, %2, %3;" : "=l"(d) : "l"(a), "l"(b), "l"(c));
    return d;
}

// Slim setup: no OOB masks (pos in [0,127] for c in [-1,1]); float clamp
// handles pos=127 (i0=126, frac=1 -> samples row 127 exactly).
__device__ __forceinline__ void setup_slim(float c, int& i0, float& fr) {
    float pos = fmaf(c, 63.5f, 63.5f);
    float f0  = floorf(pos);
    f0 = fminf(fmaxf(f0, 0.0f), 126.0f);
    i0 = (int)f0;
    fr = pos - f0;
}

// 8 centered features of one point (this lane's quarter-block channels):
// lerp bilinear in f32x2, polynomial, center by FBAR, emit 4 f16x2 regs.
__device__ __forceinline__ void feats8_c(const float* __restrict__ sT, int qoff,
                                         float cx, float cy, float cz,
                                         uint32_t* __restrict__ hreg) {
    int xi, yi, zi;
    float frx, fry, frz;
    setup_slim(cx, xi, frx);
    setup_slim(cy, yi, fry);
    setup_slim(cz, zi, frz);

    const ulonglong2* X0 = reinterpret_cast<const ulonglong2*>(&sT[(0 * LTAB + xi) * TSTRIDE + qoff]);
    const ulonglong2* Y0 = reinterpret_cast<const ulonglong2*>(&sT[(1 * LTAB + yi) * TSTRIDE + qoff]);
    const ulonglong2* Z0 = reinterpret_cast<const ulonglong2*>(&sT[(2 * LTAB + zi) * TSTRIDE + qoff]);
    // tap 1 = tap 0 + one row = +36 floats = +9 ulonglong2

    const ull frxp = pk2(frx, frx);
    const ull fryp = pk2(fry, fry);
    const ull frzp = pk2(frz, frz);
    const ull invRp  = 0x4020000040200000ull;  // {2.5f, 2.5f}
    const ull invR2p = 0x40C8000040C80000ull;  // {6.25f, 6.25f}
    const ull fbarp  = 0x3FDF40003FDF4000ull;  // {1.74375f, 1.74375f}

    ulonglong2 xa = X0[0], xb = X0[1], xc = X0[9], xd = X0[10];
    ulonglong2 ya = Y0[0], yb = Y0[1], yc = Y0[9], yd = Y0[10];
    ulonglong2 za = Z0[0], zb = Z0[1], zc = Z0[9], zd = Z0[10];

    ull xp[4] = {xa.x, xa.y, xb.x, xb.y};
    ull xq[4] = {xc.x, xc.y, xd.x, xd.y};
    ull yp[4] = {ya.x, ya.y, yb.x, yb.y};
    ull yq[4] = {yc.x, yc.y, yd.x, yd.y};
    ull zp[4] = {za.x, za.y, zb.x, zb.y};
    ull zq[4] = {zc.x, zc.y, zd.x, zd.y};

#pragma unroll
    for (int pr = 0; pr < 4; pr++) {
        ull xv = fma2(frxp, sub2(xq[pr], xp[pr]), xp[pr]);
        ull yv = fma2(fryp, sub2(yq[pr], yp[pr]), yp[pr]);
        ull zv = fma2(frzp, sub2(zq[pr], zp[pr]), zp[pr]);
        ull e  = add2(xv, yv);
        ull s  = add2(e, zv);
        ull xy = mul2(xv, yv);
        ull p2 = fma2(zv, e, xy);
        ull p3 = mul2(xy, zv);
        ull f  = fma2(p2, invRp, s);
        f = fma2(p3, invR2p, f);
        f = sub2(f, fbarp);          // center: f' = f - FBAR
        float a0, a1;
        unpk2(a0, a1, f);
        hreg[pr] = pkh(a0, a1);
    }
}

__global__ __launch_bounds__(NTHREADS, 3)
void rank1_hmma_kernel(const float* __restrict__ coords,
                       const float* __restrict__ lines,
                       const float* __restrict__ W1,
                       const float* __restrict__ b1,
                       const float* __restrict__ W2,
                       const float* __restrict__ b2,
                       float* __restrict__ out, int M) {
    extern __shared__ char smc[];
    const uint32_t sb = smem_u32(smc);
    float* sT   = reinterpret_cast<float*>(smc + SM_TAB);
    float4* sBW = reinterpret_cast<float4*>(smc + SM_BW);

    const int tid  = threadIdx.x;
    const int wid  = tid >> 5;
    const int lane = tid & 31;

    // ---- stage table: per row, 4 quarter-blocks of 8 permuted channels ----
    // block q holds channels {2q,2q+1,2q+8,2q+9,2q+16,2q+17,2q+24,2q+25}
    for (int idx = tid; idx < 3 * LTAB; idx += NTHREADS) {
        const float* src = lines + idx * CL;
        float v[CL];
#pragma unroll
        for (int j = 0; j < 8; j++) {
            float4 t4 = reinterpret_cast<const float4*>(src)[j];
            v[4 * j + 0] = t4.x; v[4 * j + 1] = t4.y;
            v[4 * j + 2] = t4.z; v[4 * j + 3] = t4.w;
        }
        float* dst = sT + idx * TSTRIDE;
#pragma unroll
        for (int q = 0; q < 4; q++) {
            dst[8 * q + 0] = v[2 * q];      dst[8 * q + 1] = v[2 * q + 1];
            dst[8 * q + 2] = v[2 * q + 8];  dst[8 * q + 3] = v[2 * q + 9];
            dst[8 * q + 4] = v[2 * q + 16]; dst[8 * q + 5] = v[2 * q + 17];
            dst[8 * q + 6] = v[2 * q + 24]; dst[8 * q + 7] = v[2 * q + 25];
        }
    }
    // ---- stage fp16 W1 rows and packed (b1',b1'',W2,W2') with FBAR fold ----
    if (tid < HDIM) {
        char* dst = smc + SM_W1 + tid * ROWPAD;
        const float4* wrow = reinterpret_cast<const float4*>(W1 + tid * CL);
        float s = 0.0f;
#pragma unroll
        for (int j = 0; j < 8; j += 2) {
            float4 wa = wrow[j], wb = wrow[j + 1];
            s += (wa.x + wa.y) + (wa.z + wa.w);
            s += (wb.x + wb.y) + (wb.z + wb.w);
            uint4 vh = make_uint4(pkh(wa.x, wa.y), pkh(wa.z, wa.w),
                                  pkh(wb.x, wb.y), pkh(wb.z, wb.w));
            *reinterpret_cast<uint4*>(dst + j * 8) = vh;
        }
        float b1p = fmaf(FBAR, s, b1[tid]);
        // scatter into packed float4: (b1'[2k], b1'[2k+1], W2[2k], W2[2k+1])
        float* bw = reinterpret_cast<float*>(sBW);
        bw[(tid >> 1) * 4 + (tid & 1)]     = b1p;
        bw[(tid >> 1) * 4 + 2 + (tid & 1)] = W2[tid];
    }
    __syncthreads();

    const float bias2 = __ldg(b2);
    const uint32_t b_addr_base =
        (sb + SM_W1) + (uint32_t)(lane & 7) * ROWPAD + (uint32_t)(lane >> 3) * 16;

    const int qoff = (lane & 3) * 8;
    const int base = lane >> 2;

    const int warp_gid    = blockIdx.x * WARPS_PER_CTA + wid;
    const int total_warps = NBLOCKS * WARPS_PER_CTA;
    const int tiles       = (M + TILE_M - 1) / TILE_M;

    for (int t = warp_gid; t < tiles; t += total_warps) {
        // ---- build centered fp16 A fragments: 8 points per lane ----
        uint32_t afr[4][2][4];   // [row-tile][k16-chunk][frag reg]
#pragma unroll
        for (int pi = 0; pi < 8; pi++) {
            int p  = t * TILE_M + base + pi * 8;
            int pc = (p < M) ? p : (M - 1);
            float cx = __ldg(&coords[3 * pc + 0]);
            float cy = __ldg(&coords[3 * pc + 1]);
            float cz = __ldg(&coords[3 * pc + 2]);
            uint32_t h[4];
            feats8_c(sT, qoff, cx, cy, cz, h);

            int rt = pi >> 1;
            int rs = pi & 1;
            afr[rt][0][rs]     = h[0];   // cols 2q,2q+1       (k chunk 0)
            afr[rt][0][2 + rs] = h[1];   // cols 2q+8,2q+9
            afr[rt][1][rs]     = h[2];   // cols 2q+16,2q+17   (k chunk 1)
            afr[rt][1][2 + rs] = h[3];   // cols 2q+24,2q+25
        }

        float oacc[8];
#pragma unroll
        for (int i = 0; i < 8; i++) oacc[i] = 0.0f;

#pragma unroll
        for (int np8 = 0; np8 < 16; np8++) {
            uint32_t bwh[4];  // [k0 lo, k0 hi, k1 lo, k1 hi] of 8 n-rows
            ldsm_x4(b_addr_base + (uint32_t)(np8 * 8) * ROWPAD, bwh);
            float4 bw = sBW[np8 * 4 + (lane & 3)];  // b1',b1'',W2,W2'

#pragma unroll
            for (int rt = 0; rt < 4; rt++) {
                float4 c = make_float4(bw.x, bw.y, bw.x, bw.y);  // folded bias
                mma_f16(c, afr[rt][0], &bwh[0]);   // f'*w k0
                mma_f16(c, afr[rt][1], &bwh[2]);   // f'*w k1
                oacc[2 * rt + 0] = fmaf(fmaxf(c.x, 0.f), bw.z, oacc[2 * rt + 0]);
                oacc[2 * rt + 0] = fmaf(fmaxf(c.y, 0.f), bw.w, oacc[2 * rt + 0]);
                oacc[2 * rt + 1] = fmaf(fmaxf(c.z, 0.f), bw.z, oacc[2 * rt + 1]);
                oacc[2 * rt + 1] = fmaf(fmaxf(c.w, 0.f), bw.w, oacc[2 * rt + 1]);
            }
        }

        // ---- reduce over the 4 lanes sharing each row, then store ----
#pragma unroll
        for (int i = 0; i < 8; i++) {
            oacc[i] += __shfl_xor_sync(0xffffffffu, oacc[i], 1);
            oacc[i] += __shfl_xor_sync(0xffffffffu, oacc[i], 2);
        }
        if ((lane & 3) == 0) {
            int pb = t * TILE_M + base;
#pragma unroll
            for (int rt = 0; rt < 4; rt++) {
                int p0 = pb + rt * 16;
                if (p0     < M) out[p0]     = oacc[2 * rt + 0] + bias2;
                if (p0 + 8 < M) out[p0 + 8] = oacc[2 * rt + 1] + bias2;
            }
        }
    }
}

extern "C" void kernel_launch(void* const* d_in, const int* in_sizes, int n_in,
                              void* d_out, int out_size) {
    const float* coords = (const float*)d_in[0];
    const float* lines  = (const float*)d_in[1];
    const float* W1     = (const float*)d_in[2];
    const float* b1     = (const float*)d_in[3];
    const float* W2     = (const float*)d_in[4];
    const float* b2     = (const float*)d_in[5];
    float* out = (float*)d_out;

    int M = in_sizes[0] / 3;

    cudaFuncSetAttribute(rank1_hmma_kernel,
                         cudaFuncAttributeMaxDynamicSharedMemorySize, SMEM_BYTES);

    rank1_hmma_kernel<<<NBLOCKS, NTHREADS, SMEM_BYTES>>>(
        coords, lines, W1, b1, W2, b2, out, M);
}